// round 4
// baseline (speedup 1.0000x reference)
#include <cuda_runtime.h>
#include <math.h>

#define NN 65536
#define EE 524288
// dims
// OBS=256 HID=512 MID=256 LSTM=256 DOUT=128 DLAST=128 RFM=256 LH=256 ACT=8

// ---------------- scratch (device globals; no allocation allowed) -------------
__device__ float g_t1[NN * 512];     // encoder hidden
__device__ float g_x[NN * 256];      // encoder out (lstm input)
__device__ float g_gates[NN * 1024]; // lstm gates
__device__ float g_nf[NN * 128];     // node features after mlp1
__device__ float g_agg[NN * 128];    // segment-sum of edge features
__device__ float g_nh[NN * 256];     // node-update hidden
__device__ float g_nf2[NN * 128];    // node-update out
__device__ float g_r1[NN * 256];     // readout hidden

// =============================================================================
// Generic tiled SGEMM: C[M,Nc] = act(A[M,K] @ W[Nc,K]^T + bias[Nc])
// BM=BN=64, BK=16, 256 threads, 4x4 register tile per thread.
// Requires: M % 64 == 0, Nc % 64 == 0, K % 16 == 0, grid = (Nc/64, M/64).
// =============================================================================
template <int RELU_A, int RELU_OUT>
__global__ __launch_bounds__(256) void gemm1_kernel(
    const float* __restrict__ A, int ldA,
    const float* __restrict__ W, int ldW, int K,
    const float* __restrict__ bias,
    float* __restrict__ C, int ldC)
{
    __shared__ float As[64][17];
    __shared__ float Ws[64][17];

    const int tid = threadIdx.x;
    const int tx = tid & 15, ty = tid >> 4;
    const int lr = tid >> 2;           // 0..63 (row within tile for loads)
    const int lk = (tid & 3) * 4;      // 0,4,8,12 (k offset for float4 loads)
    const int rowBase = blockIdx.y * 64;
    const int colBase = blockIdx.x * 64;

    float acc[4][4];
#pragma unroll
    for (int m = 0; m < 4; m++)
#pragma unroll
        for (int n = 0; n < 4; n++) acc[m][n] = 0.f;

    for (int k0 = 0; k0 < K; k0 += 16) {
        float4 av = *(const float4*)&A[(rowBase + lr) * ldA + k0 + lk];
        if (RELU_A) {
            av.x = fmaxf(av.x, 0.f); av.y = fmaxf(av.y, 0.f);
            av.z = fmaxf(av.z, 0.f); av.w = fmaxf(av.w, 0.f);
        }
        As[lr][lk + 0] = av.x; As[lr][lk + 1] = av.y;
        As[lr][lk + 2] = av.z; As[lr][lk + 3] = av.w;

        float4 wv = *(const float4*)&W[(colBase + lr) * ldW + k0 + lk];
        Ws[lr][lk + 0] = wv.x; Ws[lr][lk + 1] = wv.y;
        Ws[lr][lk + 2] = wv.z; Ws[lr][lk + 3] = wv.w;
        __syncthreads();

#pragma unroll
        for (int k = 0; k < 16; k++) {
            float a[4], b[4];
#pragma unroll
            for (int m = 0; m < 4; m++) a[m] = As[ty + m * 16][k];
#pragma unroll
            for (int n = 0; n < 4; n++) b[n] = Ws[tx + n * 16][k];
#pragma unroll
            for (int m = 0; m < 4; m++)
#pragma unroll
                for (int n = 0; n < 4; n++) acc[m][n] = fmaf(a[m], b[n], acc[m][n]);
        }
        __syncthreads();
    }

#pragma unroll
    for (int n = 0; n < 4; n++) {
        const int col = colBase + tx + n * 16;
        const float bv = bias[col];
#pragma unroll
        for (int m = 0; m < 4; m++) {
            const int row = rowBase + ty + m * 16;
            float v = acc[m][n] + bv;
            if (RELU_OUT) v = fmaxf(v, 0.f);
            C[row * ldC + col] = v;
        }
    }
}

// =============================================================================
// Dual-input SGEMM: C = act(A1@W1^T + A2@W2^T + bias1 [+ bias2])
// Used for LSTM gates and the node update (implicit concat along K).
// =============================================================================
template <int RELU_OUT>
__global__ __launch_bounds__(256) void gemm2_kernel(
    const float* __restrict__ A1, int ldA1,
    const float* __restrict__ W1, int ldW1, int K1,
    const float* __restrict__ A2, int ldA2,
    const float* __restrict__ W2, int ldW2, int K2,
    const float* __restrict__ bias1, const float* __restrict__ bias2,
    float* __restrict__ C, int ldC)
{
    __shared__ float As[64][17];
    __shared__ float Ws[64][17];

    const int tid = threadIdx.x;
    const int tx = tid & 15, ty = tid >> 4;
    const int lr = tid >> 2;
    const int lk = (tid & 3) * 4;
    const int rowBase = blockIdx.y * 64;
    const int colBase = blockIdx.x * 64;

    float acc[4][4];
#pragma unroll
    for (int m = 0; m < 4; m++)
#pragma unroll
        for (int n = 0; n < 4; n++) acc[m][n] = 0.f;

#pragma unroll 1
    for (int phase = 0; phase < 2; phase++) {
        const float* A = phase ? A2 : A1;
        const float* W = phase ? W2 : W1;
        const int ldA = phase ? ldA2 : ldA1;
        const int ldW = phase ? ldW2 : ldW1;
        const int K   = phase ? K2 : K1;
        for (int k0 = 0; k0 < K; k0 += 16) {
            float4 av = *(const float4*)&A[(rowBase + lr) * ldA + k0 + lk];
            As[lr][lk + 0] = av.x; As[lr][lk + 1] = av.y;
            As[lr][lk + 2] = av.z; As[lr][lk + 3] = av.w;
            float4 wv = *(const float4*)&W[(colBase + lr) * ldW + k0 + lk];
            Ws[lr][lk + 0] = wv.x; Ws[lr][lk + 1] = wv.y;
            Ws[lr][lk + 2] = wv.z; Ws[lr][lk + 3] = wv.w;
            __syncthreads();
#pragma unroll
            for (int k = 0; k < 16; k++) {
                float a[4], b[4];
#pragma unroll
                for (int m = 0; m < 4; m++) a[m] = As[ty + m * 16][k];
#pragma unroll
                for (int n = 0; n < 4; n++) b[n] = Ws[tx + n * 16][k];
#pragma unroll
                for (int m = 0; m < 4; m++)
#pragma unroll
                    for (int n = 0; n < 4; n++) acc[m][n] = fmaf(a[m], b[n], acc[m][n]);
            }
            __syncthreads();
        }
    }

#pragma unroll
    for (int n = 0; n < 4; n++) {
        const int col = colBase + tx + n * 16;
        float bv = bias1[col];
        if (bias2) bv += bias2[col];
#pragma unroll
        for (int m = 0; m < 4; m++) {
            const int row = rowBase + ty + m * 16;
            float v = acc[m][n] + bv;
            if (RELU_OUT) v = fmaxf(v, 0.f);
            C[row * ldC + col] = v;
        }
    }
}

// =============================================================================
// LSTM pointwise: gates[N,1024] (i,f,g,o) + c0 -> h1, c1
// =============================================================================
__device__ __forceinline__ float sigm(float x) { return 1.f / (1.f + expf(-x)); }

__global__ __launch_bounds__(256) void lstm_kernel(
    const float* __restrict__ gates, const float* __restrict__ c0,
    float* __restrict__ h1, float* __restrict__ c1)
{
    const int idx = blockIdx.x * 256 + threadIdx.x;   // N*256 total
    const int n = idx >> 8, j = idx & 255;
    const float* g = gates + n * 1024;
    const float ig = sigm(g[j]);
    const float fg = sigm(g[j + 256]);
    const float gg = tanhf(g[j + 512]);
    const float og = sigm(g[j + 768]);
    const float c = fg * c0[idx] + ig * gg;
    c1[idx] = c;
    h1[idx] = og * tanhf(c);
}

// =============================================================================
// Zero the aggregation buffer (graph-capturable, deterministic)
// =============================================================================
__global__ __launch_bounds__(256) void zero_agg_kernel()
{
    const int i = blockIdx.x * 256 + threadIdx.x;     // NN*128/4 float4s
    ((float4*)g_agg)[i] = make_float4(0.f, 0.f, 0.f, 0.f);
}

// =============================================================================
// Fused edge MLP + scatter:
//   per edge: h = relu(we[:, :128]@nf[src] + we[:, 128:]@nf[dst] + be)  (256)
//             out = we2 @ h + be2                                       (128)
//             atomicAdd(agg[dst], out)
// 64 edges per block; edge features and hidden live in smem; weight tiles
// streamed through smem (weights stay resident in L2: 384 KB total).
// =============================================================================
#define EB 64
#define SA_LD 260          // 256 + 4 pad (keeps float4 alignment, breaks bank stride)
#define EDGE_SMEM (size_t)((2 * EB * SA_LD + 64 * 17 + 64) * 4)

__global__ __launch_bounds__(256) void edge_kernel(
    const float* __restrict__ nf,
    const int* __restrict__ src, const int* __restrict__ dst,
    const float* __restrict__ we, const float* __restrict__ be,
    const float* __restrict__ we2, const float* __restrict__ be2,
    float* __restrict__ agg)
{
    extern __shared__ float esm[];
    float* sA = esm;                     // [64][SA_LD] edge input features (concat)
    float* sH = esm + EB * SA_LD;        // [64][SA_LD] hidden
    float* sW = sH + EB * SA_LD;         // [64][17] weight tile
    int*   sDst = (int*)(sW + 64 * 17);  // [64]

    const int tid = threadIdx.x;
    const int e0 = blockIdx.x * EB;

    if (tid < EB) sDst[tid] = dst[e0 + tid];

    // gather: 64 edges x 256 floats (128 from nf[src], 128 from nf[dst])
    for (int idx = tid; idx < EB * 64; idx += 256) {
        const int e = idx >> 6;          // edge in tile
        const int q = idx & 63;          // float4 index within 256-float row
        const int node = (q < 32) ? src[e0 + e] : dst[e0 + e];
        const int qq = q & 31;
        float4 v = *(const float4*)&nf[node * 128 + qq * 4];
        *(float4*)&sA[e * SA_LD + q * 4] = v;
    }
    __syncthreads();

    const int tx = tid & 15, ty = tid >> 4;
    const int lr = tid >> 2;
    const int lk = (tid & 3) * 4;

    // ---- GEMM1: sH[64,256] = relu(sA[64,256] @ we^T + be), 4 col chunks ----
#pragma unroll 1
    for (int ch = 0; ch < 4; ch++) {
        float acc[4][4];
#pragma unroll
        for (int m = 0; m < 4; m++)
#pragma unroll
            for (int n = 0; n < 4; n++) acc[m][n] = 0.f;

        for (int k0 = 0; k0 < 256; k0 += 16) {
            float4 wv = *(const float4*)&we[(ch * 64 + lr) * 256 + k0 + lk];
            sW[lr * 17 + lk + 0] = wv.x; sW[lr * 17 + lk + 1] = wv.y;
            sW[lr * 17 + lk + 2] = wv.z; sW[lr * 17 + lk + 3] = wv.w;
            __syncthreads();
#pragma unroll
            for (int k = 0; k < 16; k++) {
                float a[4], b[4];
#pragma unroll
                for (int m = 0; m < 4; m++) a[m] = sA[(ty + m * 16) * SA_LD + k0 + k];
#pragma unroll
                for (int n = 0; n < 4; n++) b[n] = sW[(tx + n * 16) * 17 + k];
#pragma unroll
                for (int m = 0; m < 4; m++)
#pragma unroll
                    for (int n = 0; n < 4; n++) acc[m][n] = fmaf(a[m], b[n], acc[m][n]);
            }
            __syncthreads();
        }
#pragma unroll
        for (int n = 0; n < 4; n++) {
            const int col = ch * 64 + tx + n * 16;
            const float bv = be[col];
#pragma unroll
            for (int m = 0; m < 4; m++) {
                const int row = ty + m * 16;
                sH[row * SA_LD + col] = fmaxf(acc[m][n] + bv, 0.f);
            }
        }
        __syncthreads();
    }

    // ---- GEMM2: out[64,128] = sH @ we2^T + be2, atomic scatter to agg ----
#pragma unroll 1
    for (int ch = 0; ch < 2; ch++) {
        float acc[4][4];
#pragma unroll
        for (int m = 0; m < 4; m++)
#pragma unroll
            for (int n = 0; n < 4; n++) acc[m][n] = 0.f;

        for (int k0 = 0; k0 < 256; k0 += 16) {
            float4 wv = *(const float4*)&we2[(ch * 64 + lr) * 256 + k0 + lk];
            sW[lr * 17 + lk + 0] = wv.x; sW[lr * 17 + lk + 1] = wv.y;
            sW[lr * 17 + lk + 2] = wv.z; sW[lr * 17 + lk + 3] = wv.w;
            __syncthreads();
#pragma unroll
            for (int k = 0; k < 16; k++) {
                float a[4], b[4];
#pragma unroll
                for (int m = 0; m < 4; m++) a[m] = sH[(ty + m * 16) * SA_LD + k0 + k];
#pragma unroll
                for (int n = 0; n < 4; n++) b[n] = sW[(tx + n * 16) * 17 + k];
#pragma unroll
                for (int m = 0; m < 4; m++)
#pragma unroll
                    for (int n = 0; n < 4; n++) acc[m][n] = fmaf(a[m], b[n], acc[m][n]);
            }
            __syncthreads();
        }
#pragma unroll
        for (int n = 0; n < 4; n++) {
            const int col = ch * 64 + tx + n * 16;
            const float bv = be2[col];
#pragma unroll
            for (int m = 0; m < 4; m++) {
                const int row = ty + m * 16;
                atomicAdd(&agg[sDst[row] * 128 + col], acc[m][n] + bv);
            }
        }
    }
}

// =============================================================================
// Readout second layer: logits[N,8] = r1[N,256] @ wr2[8,256]^T + br2
// 32 rows x 8 outputs per 256-thread block; wr2 cached in smem (padded).
// =============================================================================
__global__ __launch_bounds__(256) void logits_kernel(
    const float* __restrict__ r1, const float* __restrict__ wr2,
    const float* __restrict__ br2, float* __restrict__ out)
{
    __shared__ float sw[8 * 257];
    const int tid = threadIdx.x;
    for (int i = tid; i < 2048; i += 256) {
        sw[(i >> 8) * 257 + (i & 255)] = wr2[i];
    }
    __syncthreads();

    const int row = blockIdx.x * 32 + (tid >> 3);
    const int o = tid & 7;
    const float* a = r1 + row * 256;
    const float* w = sw + o * 257;
    float acc = 0.f;
#pragma unroll 8
    for (int k = 0; k < 256; k++) acc = fmaf(a[k], w[k], acc);
    out[row * 8 + o] = acc + br2[o];
}

// =============================================================================
// Launcher
// =============================================================================
extern "C" void kernel_launch(void* const* d_in, const int* in_sizes, int n_in,
                              void* d_out, int out_size)
{
    const float* obs  = (const float*)d_in[0];
    const float* h0   = (const float*)d_in[1];
    const float* c0   = (const float*)d_in[2];
    const int*   src  = (const int*)d_in[3];
    const int*   dst  = (const int*)d_in[4];
    const float* w1a  = (const float*)d_in[5];
    const float* b1a  = (const float*)d_in[6];
    const float* w1b  = (const float*)d_in[7];
    const float* b1b  = (const float*)d_in[8];
    const float* w_ih = (const float*)d_in[9];
    const float* b_ih = (const float*)d_in[10];
    const float* w_hh = (const float*)d_in[11];
    const float* b_hh = (const float*)d_in[12];
    const float* w1   = (const float*)d_in[13];
    const float* b1   = (const float*)d_in[14];
    const float* we   = (const float*)d_in[15];
    const float* be   = (const float*)d_in[16];
    const float* we2  = (const float*)d_in[17];
    const float* be2  = (const float*)d_in[18];
    const float* wn   = (const float*)d_in[19];
    const float* bn   = (const float*)d_in[20];
    const float* wn2  = (const float*)d_in[21];
    const float* bn2  = (const float*)d_in[22];
    const float* wr   = (const float*)d_in[23];
    const float* br   = (const float*)d_in[24];
    const float* wr2  = (const float*)d_in[25];
    const float* br2  = (const float*)d_in[26];

    float* out    = (float*)d_out;
    float* logits = out;                       // [N, 8]
    float* h1     = out + (size_t)NN * 8;      // [N, 256]
    float* c1     = h1 + (size_t)NN * 256;     // [N, 256]

    float *p_t1, *p_x, *p_gates, *p_nf, *p_agg, *p_nh, *p_nf2, *p_r1;
    cudaGetSymbolAddress((void**)&p_t1, g_t1);
    cudaGetSymbolAddress((void**)&p_x, g_x);
    cudaGetSymbolAddress((void**)&p_gates, g_gates);
    cudaGetSymbolAddress((void**)&p_nf, g_nf);
    cudaGetSymbolAddress((void**)&p_agg, g_agg);
    cudaGetSymbolAddress((void**)&p_nh, g_nh);
    cudaGetSymbolAddress((void**)&p_nf2, g_nf2);
    cudaGetSymbolAddress((void**)&p_r1, g_r1);

    cudaFuncSetAttribute(edge_kernel, cudaFuncAttributeMaxDynamicSharedMemorySize,
                         (int)EDGE_SMEM);

    const dim3 blk(256);
    const int MT = NN / 64;   // 1024 row tiles

    // 1. encoder layer 1: t1 = relu(obs @ w1a^T + b1a)          [N,512]
    gemm1_kernel<0, 1><<<dim3(512 / 64, MT), blk>>>(obs, 256, w1a, 256, 256, b1a, p_t1, 512);
    // 2. encoder layer 2: x = t1 @ w1b^T + b1b                  [N,256]
    gemm1_kernel<0, 0><<<dim3(256 / 64, MT), blk>>>(p_t1, 512, w1b, 512, 512, b1b, p_x, 256);
    // 3. gates = x @ w_ih^T + h0 @ w_hh^T + b_ih + b_hh         [N,1024]
    gemm2_kernel<0><<<dim3(1024 / 64, MT), blk>>>(p_x, 256, w_ih, 256, 256,
                                                  h0, 256, w_hh, 256, 256,
                                                  b_ih, b_hh, p_gates, 1024);
    // 4. LSTM pointwise -> h1, c1 (directly into output buffer)
    lstm_kernel<<<NN * 256 / 256, blk>>>(p_gates, c0, h1, c1);
    // 5. nf = relu(h1) @ w1^T + b1                              [N,128]
    gemm1_kernel<1, 0><<<dim3(128 / 64, MT), blk>>>(h1, 256, w1, 256, 256, b1, p_nf, 128);
    // 6. zero agg
    zero_agg_kernel<<<NN * 128 / 4 / 256, blk>>>();
    // 7. fused edge MLP + scatter
    edge_kernel<<<EE / EB, blk, EDGE_SMEM>>>(p_nf, src, dst, we, be, we2, be2, p_agg);
    // 8. node hidden = relu([nf | agg] @ wn^T + bn)             [N,256]
    gemm2_kernel<1><<<dim3(256 / 64, MT), blk>>>(p_nf, 128, wn, 256, 128,
                                                 p_agg, 128, wn + 128, 256, 128,
                                                 bn, nullptr, p_nh, 256);
    // 9. nf2 = nh @ wn2^T + bn2                                 [N,128]
    gemm1_kernel<0, 0><<<dim3(128 / 64, MT), blk>>>(p_nh, 256, wn2, 256, 256, bn2, p_nf2, 128);
    // 10. r1 = relu(nf2 @ wr^T + br)                            [N,256]
    gemm1_kernel<0, 1><<<dim3(256 / 64, MT), blk>>>(p_nf2, 128, wr, 128, 128, br, p_r1, 256);
    // 11. logits = r1 @ wr2^T + br2                             [N,8]
    logits_kernel<<<NN / 32, blk>>>(p_r1, wr2, br2, logits);
}

// round 5
// speedup vs baseline: 2.2972x; 2.2972x over previous
#include <cuda_runtime.h>
#include <math.h>
#include <stdint.h>

#define NN 65536
#define EE 524288
// dims: OBS=256 HID=512 MID=256 LSTM=256 DOUT=128 DLAST=128 RFM=256 LH=256 ACT=8

// ---------------- scratch (device globals; no allocation allowed) -------------
__device__ float g_t1[NN * 512];
__device__ float g_x[NN * 256];
__device__ float g_gates[NN * 1024];
__device__ float g_nf[NN * 128];
__device__ float g_U[NN * 256];      // nf @ weL^T + be   (per-node edge-src term)
__device__ float g_V[NN * 256];      // nf @ weR^T        (per-node edge-dst term)
__device__ float g_aggH[NN * 256];   // segment-sum of edge hidden
__device__ float g_deg[NN];          // in-degree (float)
__device__ float g_aggE[NN * 128];   // aggH @ we2^T + deg*be2
__device__ float g_nh[NN * 256];
__device__ float g_nf2[NN * 128];
__device__ float g_r1[NN * 256];

// ---------------------------- tf32 helpers -----------------------------------
__device__ __forceinline__ float tf32_rn(float x) {
    uint32_t u;
    asm("cvt.rna.tf32.f32 %0, %1;" : "=r"(u) : "f"(x));
    return __uint_as_float(u);
}

__device__ __forceinline__ void mma8(float* d, const uint32_t* a, const uint32_t* b) {
    asm volatile(
        "mma.sync.aligned.m16n8k8.row.col.f32.tf32.tf32.f32 "
        "{%0,%1,%2,%3}, {%4,%5,%6,%7}, {%8,%9}, {%0,%1,%2,%3};"
        : "+f"(d[0]), "+f"(d[1]), "+f"(d[2]), "+f"(d[3])
        : "r"(a[0]), "r"(a[1]), "r"(a[2]), "r"(a[3]), "r"(b[0]), "r"(b[1]));
}

// =============================================================================
// TF32x3 tensor-core GEMM: C[M,Nc] = act(A@W^T [+ A2@W2^T] + bias [+bias2])
// BM=128, BN=64, BK=16; 256 threads = 8 warps in 4(m) x 2(n); warp tile 32x32.
// hi/lo tf32 split precomputed into smem once per tile (3xtf32 ~ fp32 accuracy).
// DEGBIAS: v = acc + deg[row]*bias[col]  (for the aggregated-edge bias term).
// Requires M%128==0, Nc%64==0, K%16==0; DUAL phases share ldA/ldW/K.
// =============================================================================
#define BKP 20

template <int RELU_A, int RELU_OUT, int DEGBIAS, int DUAL>
__global__ __launch_bounds__(256) void tgemm(
    const float* __restrict__ A, const float* __restrict__ A2, int ldA,
    const float* __restrict__ W, const float* __restrict__ W2, int ldW, int K,
    const float* __restrict__ bias, const float* __restrict__ bias2,
    const float* __restrict__ deg,
    float* __restrict__ C, int ldC)
{
    __shared__ float Ah[128][BKP], Al[128][BKP];
    __shared__ float Wh[64][BKP],  Wl[64][BKP];

    const int tid = threadIdx.x;
    const int warp = tid >> 5, lane = tid & 31;
    const int wy = warp >> 1, wx = warp & 1;   // 4 x 2 warp grid
    const int g = lane >> 2, tg = lane & 3;    // group / thread-in-group
    const int rowBase = blockIdx.y * 128;
    const int colBase = blockIdx.x * 64;
    const int lr = tid >> 2;                   // 0..63
    const int lc = (tid & 3) * 4;              // 0,4,8,12

    float acc[2][4][4];
#pragma unroll
    for (int i = 0; i < 2; i++)
#pragma unroll
        for (int j = 0; j < 4; j++)
#pragma unroll
            for (int k = 0; k < 4; k++) acc[i][j][k] = 0.f;

#pragma unroll 1
    for (int ph = 0; ph < (DUAL ? 2 : 1); ph++) {
        const float* pA = ph ? A2 : A;
        const float* pW = ph ? W2 : W;
        for (int k0 = 0; k0 < K; k0 += 16) {
            // load + split A tile (128x16): 2 float4 per thread
#pragma unroll
            for (int h = 0; h < 2; h++) {
                const int r = lr + 64 * h;
                float4 av = *(const float4*)&pA[(size_t)(rowBase + r) * ldA + k0 + lc];
                if (RELU_A) {
                    av.x = fmaxf(av.x, 0.f); av.y = fmaxf(av.y, 0.f);
                    av.z = fmaxf(av.z, 0.f); av.w = fmaxf(av.w, 0.f);
                }
                float hv;
                hv = tf32_rn(av.x); Ah[r][lc + 0] = hv; Al[r][lc + 0] = tf32_rn(av.x - hv);
                hv = tf32_rn(av.y); Ah[r][lc + 1] = hv; Al[r][lc + 1] = tf32_rn(av.y - hv);
                hv = tf32_rn(av.z); Ah[r][lc + 2] = hv; Al[r][lc + 2] = tf32_rn(av.z - hv);
                hv = tf32_rn(av.w); Ah[r][lc + 3] = hv; Al[r][lc + 3] = tf32_rn(av.w - hv);
            }
            // load + split W tile (64x16): 1 float4 per thread
            {
                float4 wv = *(const float4*)&pW[(size_t)(colBase + lr) * ldW + k0 + lc];
                float hv;
                hv = tf32_rn(wv.x); Wh[lr][lc + 0] = hv; Wl[lr][lc + 0] = tf32_rn(wv.x - hv);
                hv = tf32_rn(wv.y); Wh[lr][lc + 1] = hv; Wl[lr][lc + 1] = tf32_rn(wv.y - hv);
                hv = tf32_rn(wv.z); Wh[lr][lc + 2] = hv; Wl[lr][lc + 2] = tf32_rn(wv.z - hv);
                hv = tf32_rn(wv.w); Wh[lr][lc + 3] = hv; Wl[lr][lc + 3] = tf32_rn(wv.w - hv);
            }
            __syncthreads();

#pragma unroll
            for (int kk = 0; kk < 16; kk += 8) {
                uint32_t ah[2][4], al[2][4], bh[4][2], bl[4][2];
#pragma unroll
                for (int mt = 0; mt < 2; mt++) {
                    const int r = wy * 32 + mt * 16 + g;
                    ah[mt][0] = __float_as_uint(Ah[r][kk + tg]);
                    ah[mt][1] = __float_as_uint(Ah[r + 8][kk + tg]);
                    ah[mt][2] = __float_as_uint(Ah[r][kk + tg + 4]);
                    ah[mt][3] = __float_as_uint(Ah[r + 8][kk + tg + 4]);
                    al[mt][0] = __float_as_uint(Al[r][kk + tg]);
                    al[mt][1] = __float_as_uint(Al[r + 8][kk + tg]);
                    al[mt][2] = __float_as_uint(Al[r][kk + tg + 4]);
                    al[mt][3] = __float_as_uint(Al[r + 8][kk + tg + 4]);
                }
#pragma unroll
                for (int nt = 0; nt < 4; nt++) {
                    const int n = wx * 32 + nt * 8 + g;
                    bh[nt][0] = __float_as_uint(Wh[n][kk + tg]);
                    bh[nt][1] = __float_as_uint(Wh[n][kk + tg + 4]);
                    bl[nt][0] = __float_as_uint(Wl[n][kk + tg]);
                    bl[nt][1] = __float_as_uint(Wl[n][kk + tg + 4]);
                }
#pragma unroll
                for (int mt = 0; mt < 2; mt++)
#pragma unroll
                    for (int nt = 0; nt < 4; nt++) {
                        mma8(acc[mt][nt], ah[mt], bh[nt]);
                        mma8(acc[mt][nt], ah[mt], bl[nt]);
                        mma8(acc[mt][nt], al[mt], bh[nt]);
                    }
            }
            __syncthreads();
        }
    }

    // epilogue
#pragma unroll
    for (int mt = 0; mt < 2; mt++) {
        const int row = rowBase + wy * 32 + mt * 16 + g;
        const float d0 = DEGBIAS ? deg[row] : 1.f;
        const float d1 = DEGBIAS ? deg[row + 8] : 1.f;
#pragma unroll
        for (int nt = 0; nt < 4; nt++) {
            const int col = colBase + wx * 32 + nt * 8 + 2 * tg;
            float bb0 = 0.f, bb1 = 0.f;
            if (bias)  { bb0 = bias[col];  bb1 = bias[col + 1]; }
            if (DUAL && bias2) { bb0 += bias2[col]; bb1 += bias2[col + 1]; }
            float v0 = acc[mt][nt][0] + d0 * bb0;
            float v1 = acc[mt][nt][1] + d0 * bb1;
            float v2 = acc[mt][nt][2] + d1 * bb0;
            float v3 = acc[mt][nt][3] + d1 * bb1;
            if (RELU_OUT) {
                v0 = fmaxf(v0, 0.f); v1 = fmaxf(v1, 0.f);
                v2 = fmaxf(v2, 0.f); v3 = fmaxf(v3, 0.f);
            }
            *(float2*)&C[(size_t)row * ldC + col]       = make_float2(v0, v1);
            *(float2*)&C[(size_t)(row + 8) * ldC + col] = make_float2(v2, v3);
        }
    }
}

// =============================================================================
// LSTM pointwise: gates[N,1024] (i,f,g,o) + c0 -> h1, c1
// =============================================================================
__device__ __forceinline__ float sigm(float x) { return 1.f / (1.f + expf(-x)); }

__global__ __launch_bounds__(256) void lstm_kernel(
    const float* __restrict__ gates, const float* __restrict__ c0,
    float* __restrict__ h1, float* __restrict__ c1)
{
    const int idx = blockIdx.x * 256 + threadIdx.x;   // N*256 total
    const int n = idx >> 8, j = idx & 255;
    const float* g = gates + (size_t)n * 1024;
    const float ig = sigm(g[j]);
    const float fg = sigm(g[j + 256]);
    const float gg = tanhf(g[j + 512]);
    const float og = sigm(g[j + 768]);
    const float c = fg * c0[idx] + ig * gg;
    c1[idx] = c;
    h1[idx] = og * tanhf(c);
}

// =============================================================================
// Zero helper (graph-capturable, deterministic)
// =============================================================================
__global__ __launch_bounds__(256) void zero4_kernel(float4* __restrict__ p)
{
    p[blockIdx.x * 256 + threadIdx.x] = make_float4(0.f, 0.f, 0.f, 0.f);
}

// =============================================================================
// Edge stage (pure memory): h = relu(U[src] + V[dst]); aggH[dst] += h; deg[dst]++
// One warp per edge; 8 edges per 256-thread block.
// =============================================================================
__global__ __launch_bounds__(256) void edge_scatter_kernel(
    const float* __restrict__ U, const float* __restrict__ V,
    const int* __restrict__ src, const int* __restrict__ dst,
    float* __restrict__ aggH, float* __restrict__ deg)
{
    const int e = blockIdx.x * 8 + (threadIdx.x >> 5);
    const int lane = threadIdx.x & 31;
    const int s = src[e], d = dst[e];
    const float4* u = (const float4*)(U + (size_t)s * 256);
    const float4* v = (const float4*)(V + (size_t)d * 256);
    float* a = aggH + (size_t)d * 256;
#pragma unroll
    for (int i = 0; i < 2; i++) {
        const int q = lane + 32 * i;
        float4 uu = u[q], vv = v[q];
        const float h0 = fmaxf(uu.x + vv.x, 0.f);
        const float h1 = fmaxf(uu.y + vv.y, 0.f);
        const float h2 = fmaxf(uu.z + vv.z, 0.f);
        const float h3 = fmaxf(uu.w + vv.w, 0.f);
        atomicAdd(a + q * 4 + 0, h0);
        atomicAdd(a + q * 4 + 1, h1);
        atomicAdd(a + q * 4 + 2, h2);
        atomicAdd(a + q * 4 + 3, h3);
    }
    if (lane == 0) atomicAdd(deg + d, 1.0f);
}

// =============================================================================
// Readout second layer: logits[N,8] = r1[N,256] @ wr2[8,256]^T + br2
// =============================================================================
__global__ __launch_bounds__(256) void logits_kernel(
    const float* __restrict__ r1, const float* __restrict__ wr2,
    const float* __restrict__ br2, float* __restrict__ out)
{
    __shared__ float sw[8 * 257];
    const int tid = threadIdx.x;
    for (int i = tid; i < 2048; i += 256)
        sw[(i >> 8) * 257 + (i & 255)] = wr2[i];
    __syncthreads();

    const int row = blockIdx.x * 32 + (tid >> 3);
    const int o = tid & 7;
    const float* a = r1 + (size_t)row * 256;
    const float* w = sw + o * 257;
    float acc = 0.f;
#pragma unroll 8
    for (int k = 0; k < 256; k++) acc = fmaf(a[k], w[k], acc);
    out[(size_t)row * 8 + o] = acc + br2[o];
}

// =============================================================================
// Launcher
// =============================================================================
extern "C" void kernel_launch(void* const* d_in, const int* in_sizes, int n_in,
                              void* d_out, int out_size)
{
    const float* obs  = (const float*)d_in[0];
    const float* h0   = (const float*)d_in[1];
    const float* c0   = (const float*)d_in[2];
    const int*   src  = (const int*)d_in[3];
    const int*   dst  = (const int*)d_in[4];
    const float* w1a  = (const float*)d_in[5];
    const float* b1a  = (const float*)d_in[6];
    const float* w1b  = (const float*)d_in[7];
    const float* b1b  = (const float*)d_in[8];
    const float* w_ih = (const float*)d_in[9];
    const float* b_ih = (const float*)d_in[10];
    const float* w_hh = (const float*)d_in[11];
    const float* b_hh = (const float*)d_in[12];
    const float* w1   = (const float*)d_in[13];
    const float* b1   = (const float*)d_in[14];
    const float* we   = (const float*)d_in[15];
    const float* be   = (const float*)d_in[16];
    const float* we2  = (const float*)d_in[17];
    const float* be2  = (const float*)d_in[18];
    const float* wn   = (const float*)d_in[19];
    const float* bn   = (const float*)d_in[20];
    const float* wn2  = (const float*)d_in[21];
    const float* bn2  = (const float*)d_in[22];
    const float* wr   = (const float*)d_in[23];
    const float* br   = (const float*)d_in[24];
    const float* wr2  = (const float*)d_in[25];
    const float* br2  = (const float*)d_in[26];

    float* out    = (float*)d_out;
    float* logits = out;                       // [N, 8]
    float* h1     = out + (size_t)NN * 8;      // [N, 256]
    float* c1     = h1 + (size_t)NN * 256;     // [N, 256]

    float *p_t1, *p_x, *p_gates, *p_nf, *p_U, *p_V, *p_aggH, *p_deg, *p_aggE,
          *p_nh, *p_nf2, *p_r1;
    cudaGetSymbolAddress((void**)&p_t1, g_t1);
    cudaGetSymbolAddress((void**)&p_x, g_x);
    cudaGetSymbolAddress((void**)&p_gates, g_gates);
    cudaGetSymbolAddress((void**)&p_nf, g_nf);
    cudaGetSymbolAddress((void**)&p_U, g_U);
    cudaGetSymbolAddress((void**)&p_V, g_V);
    cudaGetSymbolAddress((void**)&p_aggH, g_aggH);
    cudaGetSymbolAddress((void**)&p_deg, g_deg);
    cudaGetSymbolAddress((void**)&p_aggE, g_aggE);
    cudaGetSymbolAddress((void**)&p_nh, g_nh);
    cudaGetSymbolAddress((void**)&p_nf2, g_nf2);
    cudaGetSymbolAddress((void**)&p_r1, g_r1);

    const dim3 blk(256);
    const int MT = NN / 128;   // 512 row tiles

    // 1. t1 = relu(obs @ w1a^T + b1a)                        [N,512] K=256
    tgemm<0, 1, 0, 0><<<dim3(8, MT), blk>>>(obs, nullptr, 256, w1a, nullptr, 256, 256,
                                            b1a, nullptr, nullptr, p_t1, 512);
    // 2. x = t1 @ w1b^T + b1b                                [N,256] K=512
    tgemm<0, 0, 0, 0><<<dim3(4, MT), blk>>>(p_t1, nullptr, 512, w1b, nullptr, 512, 512,
                                            b1b, nullptr, nullptr, p_x, 256);
    // 3. gates = x@w_ih^T + h0@w_hh^T + b_ih + b_hh          [N,1024]
    tgemm<0, 0, 0, 1><<<dim3(16, MT), blk>>>(p_x, h0, 256, w_ih, w_hh, 256, 256,
                                             b_ih, b_hh, nullptr, p_gates, 1024);
    // 4. LSTM pointwise -> h1, c1 (into output buffer)
    lstm_kernel<<<NN, blk>>>(p_gates, c0, h1, c1);
    // 5. nf = relu(h1) @ w1^T + b1                           [N,128] K=256
    tgemm<1, 0, 0, 0><<<dim3(2, MT), blk>>>(h1, nullptr, 256, w1, nullptr, 256, 256,
                                            b1, nullptr, nullptr, p_nf, 128);
    // 6. zero aggH + deg
    zero4_kernel<<<NN * 256 / 4 / 256, blk>>>((float4*)p_aggH);
    zero4_kernel<<<NN / 4 / 256, blk>>>((float4*)p_deg);
    // 7a. U = nf @ weL^T + be                                [N,256] K=128
    tgemm<0, 0, 0, 0><<<dim3(4, MT), blk>>>(p_nf, nullptr, 128, we, nullptr, 256, 128,
                                            be, nullptr, nullptr, p_U, 256);
    // 7b. V = nf @ weR^T                                     [N,256] K=128
    tgemm<0, 0, 0, 0><<<dim3(4, MT), blk>>>(p_nf, nullptr, 128, we + 128, nullptr, 256, 128,
                                            nullptr, nullptr, nullptr, p_V, 256);
    // 8. edge scatter: aggH[dst] += relu(U[src]+V[dst]); deg[dst]++
    edge_scatter_kernel<<<EE / 8, blk>>>(p_U, p_V, src, dst, p_aggH, p_deg);
    // 9. aggE = aggH @ we2^T + deg*be2                       [N,128] K=256
    tgemm<0, 0, 1, 0><<<dim3(2, MT), blk>>>(p_aggH, nullptr, 256, we2, nullptr, 256, 256,
                                            be2, nullptr, p_deg, p_aggE, 128);
    // 10. nh = relu(nf@wnL^T + aggE@wnR^T + bn)              [N,256]
    tgemm<0, 1, 0, 1><<<dim3(4, MT), blk>>>(p_nf, p_aggE, 128, wn, wn + 128, 256, 128,
                                            bn, nullptr, nullptr, p_nh, 256);
    // 11. nf2 = nh @ wn2^T + bn2                             [N,128] K=256
    tgemm<0, 0, 0, 0><<<dim3(2, MT), blk>>>(p_nh, nullptr, 256, wn2, nullptr, 256, 256,
                                            bn2, nullptr, nullptr, p_nf2, 128);
    // 12. r1 = relu(nf2 @ wr^T + br)                         [N,256] K=128
    tgemm<0, 1, 0, 0><<<dim3(4, MT), blk>>>(p_nf2, nullptr, 128, wr, nullptr, 128, 128,
                                            br, nullptr, nullptr, p_r1, 256);
    // 13. logits = r1 @ wr2^T + br2                          [N,8]
    logits_kernel<<<NN / 32, blk>>>(p_r1, wr2, br2, logits);
}

// round 6
// speedup vs baseline: 3.1974x; 1.3918x over previous
#include <cuda_runtime.h>
#include <cuda_bf16.h>
#include <math.h>
#include <stdint.h>

#define NN 65536
#define EE 524288
// dims: OBS=256 HID=512 MID=256 LSTM=256 DOUT=128 DLAST=128 RFM=256 LH=256 ACT=8

// ---------------- scratch (device globals; no allocation allowed) -------------
__device__ float g_t1[NN * 512];
__device__ float g_x[NN * 256];
__device__ float g_gates[NN * 1024];
__device__ float g_nf[NN * 128];
__device__ float g_U[NN * 256];      // nf @ weL^T + be
__device__ float g_V[NN * 256];      // nf @ weR^T
__device__ float g_aggH[NN * 256];   // segment-sum of edge hidden
__device__ float g_deg[NN];          // in-degree (float)
__device__ float g_aggE[NN * 128];   // aggH @ we2^T + deg*be2
__device__ float g_nh[NN * 256];
__device__ float g_nf2[NN * 128];
__device__ float g_r1[NN * 256];
// CSR machinery
__device__ int g_cnt[NN];
__device__ int g_csr[NN];
__device__ int g_cur[NN];
__device__ int g_eid[EE];
__device__ int g_bsum[256];

// ---------------------------- bf16 / mma helpers ------------------------------
__device__ __forceinline__ uint32_t pk(__nv_bfloat16 a, __nv_bfloat16 b) {
    return (uint32_t)__bfloat16_as_ushort(a) |
           ((uint32_t)__bfloat16_as_ushort(b) << 16);
}

__device__ __forceinline__ void mma16(float* d, const uint32_t* a, const uint32_t* b) {
    asm volatile(
        "mma.sync.aligned.m16n8k16.row.col.f32.bf16.bf16.f32 "
        "{%0,%1,%2,%3}, {%4,%5,%6,%7}, {%8,%9}, {%0,%1,%2,%3};"
        : "+f"(d[0]), "+f"(d[1]), "+f"(d[2]), "+f"(d[3])
        : "r"(a[0]), "r"(a[1]), "r"(a[2]), "r"(a[3]), "r"(b[0]), "r"(b[1]));
}

__device__ __forceinline__ void ldsm4(uint32_t* r, uint32_t addr) {
    asm volatile(
        "ldmatrix.sync.aligned.m8n8.x4.shared.b16 {%0,%1,%2,%3}, [%4];"
        : "=r"(r[0]), "=r"(r[1]), "=r"(r[2]), "=r"(r[3]) : "r"(addr));
}

// =============================================================================
// BF16x3 tensor-core GEMM: C[M,Nc] = act(A@W^T [+ A2@W2^T] + bias [+bias2])
// BM=128, BN=64, BK=32; 256 threads = 8 warps (4m x 2n); warp tile 32x32.
// A = Ah + Al (bf16 hi/lo split); 3 products (hh, hl, lh) ~ fp32 accuracy.
// Fragments loaded with ldmatrix.x4; smem pitch 40 bf16 (80B) => conflict-free.
// DEGBIAS: v = acc + deg[row]*bias[col]. Requires M%128==0, Nc%64==0, K%32==0.
// =============================================================================
#define AP 40

template <int RELU_A, int RELU_OUT, int DEGBIAS, int DUAL>
__global__ __launch_bounds__(256) void tgemm(
    const float* __restrict__ A, const float* __restrict__ A2, int ldA,
    const float* __restrict__ W, const float* __restrict__ W2, int ldW, int K,
    const float* __restrict__ bias, const float* __restrict__ bias2,
    const float* __restrict__ deg,
    float* __restrict__ C, int ldC)
{
    __shared__ __nv_bfloat16 Ah[128 * AP], Al[128 * AP];
    __shared__ __nv_bfloat16 Wh[64 * AP],  Wl[64 * AP];

    const int tid = threadIdx.x;
    const int warp = tid >> 5, lane = tid & 31;
    const int wy = warp >> 1, wx = warp & 1;     // 4 x 2 warp grid
    const int g = lane >> 2, tg = lane & 3;
    const int rowBase = blockIdx.y * 128;
    const int colBase = blockIdx.x * 64;

    const uint32_t aHi = (uint32_t)__cvta_generic_to_shared(Ah);
    const uint32_t aLo = (uint32_t)__cvta_generic_to_shared(Al);
    const uint32_t wHi = (uint32_t)__cvta_generic_to_shared(Wh);
    const uint32_t wLo = (uint32_t)__cvta_generic_to_shared(Wl);

    float acc[2][4][4];
#pragma unroll
    for (int i = 0; i < 2; i++)
#pragma unroll
        for (int j = 0; j < 4; j++)
#pragma unroll
            for (int k = 0; k < 4; k++) acc[i][j][k] = 0.f;

#pragma unroll 1
    for (int ph = 0; ph < (DUAL ? 2 : 1); ph++) {
        const float* pA = ph ? A2 : A;
        const float* pW = ph ? W2 : W;
#pragma unroll 1
        for (int k0 = 0; k0 < K; k0 += 32) {
            // ---- load + split A tile (128x32): 4 float4 per thread ----
#pragma unroll
            for (int i = 0; i < 4; i++) {
                const int idx = tid + 256 * i;
                const int r = idx >> 3;
                const int c = (idx & 7) * 4;
                float4 av = *(const float4*)&pA[(size_t)(rowBase + r) * ldA + k0 + c];
                if (RELU_A) {
                    av.x = fmaxf(av.x, 0.f); av.y = fmaxf(av.y, 0.f);
                    av.z = fmaxf(av.z, 0.f); av.w = fmaxf(av.w, 0.f);
                }
                __nv_bfloat16 h0 = __float2bfloat16_rn(av.x);
                __nv_bfloat16 h1 = __float2bfloat16_rn(av.y);
                __nv_bfloat16 h2 = __float2bfloat16_rn(av.z);
                __nv_bfloat16 h3 = __float2bfloat16_rn(av.w);
                __nv_bfloat16 l0 = __float2bfloat16_rn(av.x - __bfloat162float(h0));
                __nv_bfloat16 l1 = __float2bfloat16_rn(av.y - __bfloat162float(h1));
                __nv_bfloat16 l2 = __float2bfloat16_rn(av.z - __bfloat162float(h2));
                __nv_bfloat16 l3 = __float2bfloat16_rn(av.w - __bfloat162float(h3));
                uint32_t* ph32 = (uint32_t*)&Ah[r * AP + c];
                ph32[0] = pk(h0, h1); ph32[1] = pk(h2, h3);
                uint32_t* pl32 = (uint32_t*)&Al[r * AP + c];
                pl32[0] = pk(l0, l1); pl32[1] = pk(l2, l3);
            }
            // ---- load + split W tile (64x32): 2 float4 per thread ----
#pragma unroll
            for (int i = 0; i < 2; i++) {
                const int idx = tid + 256 * i;
                const int r = idx >> 3;
                const int c = (idx & 7) * 4;
                float4 wv = *(const float4*)&pW[(size_t)(colBase + r) * ldW + k0 + c];
                __nv_bfloat16 h0 = __float2bfloat16_rn(wv.x);
                __nv_bfloat16 h1 = __float2bfloat16_rn(wv.y);
                __nv_bfloat16 h2 = __float2bfloat16_rn(wv.z);
                __nv_bfloat16 h3 = __float2bfloat16_rn(wv.w);
                __nv_bfloat16 l0 = __float2bfloat16_rn(wv.x - __bfloat162float(h0));
                __nv_bfloat16 l1 = __float2bfloat16_rn(wv.y - __bfloat162float(h1));
                __nv_bfloat16 l2 = __float2bfloat16_rn(wv.z - __bfloat162float(h2));
                __nv_bfloat16 l3 = __float2bfloat16_rn(wv.w - __bfloat162float(h3));
                uint32_t* ph32 = (uint32_t*)&Wh[r * AP + c];
                ph32[0] = pk(h0, h1); ph32[1] = pk(h2, h3);
                uint32_t* pl32 = (uint32_t*)&Wl[r * AP + c];
                pl32[0] = pk(l0, l1); pl32[1] = pk(l2, l3);
            }
            __syncthreads();

#pragma unroll
            for (int kk = 0; kk < 32; kk += 16) {
                uint32_t ah[2][4], alf[2][4], bh[2][4], bl[2][4];
#pragma unroll
                for (int mt = 0; mt < 2; mt++) {
                    const int row = wy * 32 + mt * 16 + (lane & 15);
                    const int col = kk + ((lane >> 4) << 3);
                    const uint32_t off = (uint32_t)(row * AP + col) * 2;
                    ldsm4(ah[mt], aHi + off);
                    ldsm4(alf[mt], aLo + off);
                }
#pragma unroll
                for (int nb = 0; nb < 2; nb++) {
                    const int row = wx * 32 + nb * 16 + (lane & 7) + (((lane >> 4) & 1) << 3);
                    const int col = kk + (((lane >> 3) & 1) << 3);
                    const uint32_t off = (uint32_t)(row * AP + col) * 2;
                    ldsm4(bh[nb], wHi + off);
                    ldsm4(bl[nb], wLo + off);
                }
#pragma unroll
                for (int mt = 0; mt < 2; mt++)
#pragma unroll
                    for (int nb = 0; nb < 2; nb++) {
                        mma16(acc[mt][nb * 2],     ah[mt],  &bh[nb][0]);
                        mma16(acc[mt][nb * 2],     ah[mt],  &bl[nb][0]);
                        mma16(acc[mt][nb * 2],     alf[mt], &bh[nb][0]);
                        mma16(acc[mt][nb * 2 + 1], ah[mt],  &bh[nb][2]);
                        mma16(acc[mt][nb * 2 + 1], ah[mt],  &bl[nb][2]);
                        mma16(acc[mt][nb * 2 + 1], alf[mt], &bh[nb][2]);
                    }
            }
            __syncthreads();
        }
    }

    // epilogue (acc[mt][nt]: rows g,g+8 of mt*16; cols (nt>>1)*16+(nt&1)*8+2tg)
#pragma unroll
    for (int mt = 0; mt < 2; mt++) {
        const int row = rowBase + wy * 32 + mt * 16 + g;
        const float d0 = DEGBIAS ? deg[row] : 1.f;
        const float d1 = DEGBIAS ? deg[row + 8] : 1.f;
#pragma unroll
        for (int nt = 0; nt < 4; nt++) {
            const int col = colBase + wx * 32 + ((nt >> 1) << 4) + ((nt & 1) << 3) + 2 * tg;
            float bb0 = 0.f, bb1 = 0.f;
            if (bias)  { bb0 = bias[col];  bb1 = bias[col + 1]; }
            if (DUAL && bias2) { bb0 += bias2[col]; bb1 += bias2[col + 1]; }
            float v0 = acc[mt][nt][0] + d0 * bb0;
            float v1 = acc[mt][nt][1] + d0 * bb1;
            float v2 = acc[mt][nt][2] + d1 * bb0;
            float v3 = acc[mt][nt][3] + d1 * bb1;
            if (RELU_OUT) {
                v0 = fmaxf(v0, 0.f); v1 = fmaxf(v1, 0.f);
                v2 = fmaxf(v2, 0.f); v3 = fmaxf(v3, 0.f);
            }
            *(float2*)&C[(size_t)row * ldC + col]       = make_float2(v0, v1);
            *(float2*)&C[(size_t)(row + 8) * ldC + col] = make_float2(v2, v3);
        }
    }
}

// =============================================================================
// LSTM pointwise
// =============================================================================
__device__ __forceinline__ float sigm(float x) { return 1.f / (1.f + expf(-x)); }

__global__ __launch_bounds__(256) void lstm_kernel(
    const float* __restrict__ gates, const float* __restrict__ c0,
    float* __restrict__ h1, float* __restrict__ c1)
{
    const int idx = blockIdx.x * 256 + threadIdx.x;
    const int n = idx >> 8, j = idx & 255;
    const float* g = gates + (size_t)n * 1024;
    const float ig = sigm(g[j]);
    const float fg = sigm(g[j + 256]);
    const float gg = tanhf(g[j + 512]);
    const float og = sigm(g[j + 768]);
    const float c = fg * c0[idx] + ig * gg;
    c1[idx] = c;
    h1[idx] = og * tanhf(c);
}

// =============================================================================
// CSR build: histogram -> 2-level exclusive scan -> id scatter
// =============================================================================
__global__ __launch_bounds__(256) void zero_int_kernel(int* __restrict__ p)
{
    p[blockIdx.x * 256 + threadIdx.x] = 0;
}

__global__ __launch_bounds__(256) void hist_kernel(const int* __restrict__ dst,
                                                   int* __restrict__ cnt)
{
    atomicAdd(&cnt[dst[blockIdx.x * 256 + threadIdx.x]], 1);
}

__global__ __launch_bounds__(256) void scan1_kernel(
    const int* __restrict__ cnt, int* __restrict__ csr, int* __restrict__ bsum)
{
    __shared__ int s[256];
    const int t = threadIdx.x, b = blockIdx.x;
    const int v = cnt[b * 256 + t];
    s[t] = v; __syncthreads();
#pragma unroll
    for (int off = 1; off < 256; off <<= 1) {
        int x = (t >= off) ? s[t - off] : 0;
        __syncthreads();
        s[t] += x;
        __syncthreads();
    }
    csr[b * 256 + t] = s[t] - v;
    if (t == 255) bsum[b] = s[255];
}

__global__ __launch_bounds__(256) void scan2_kernel(int* __restrict__ bsum)
{
    __shared__ int s[256];
    const int t = threadIdx.x;
    const int v = bsum[t];
    s[t] = v; __syncthreads();
#pragma unroll
    for (int off = 1; off < 256; off <<= 1) {
        int x = (t >= off) ? s[t - off] : 0;
        __syncthreads();
        s[t] += x;
        __syncthreads();
    }
    bsum[t] = s[t] - v;
}

__global__ __launch_bounds__(256) void scan3_kernel(
    int* __restrict__ csr, const int* __restrict__ bsum, int* __restrict__ cur)
{
    const int i = blockIdx.x * 256 + threadIdx.x;
    const int x = csr[i] + bsum[i >> 8];
    csr[i] = x;
    cur[i] = x;
}

__global__ __launch_bounds__(256) void scatter_id_kernel(
    const int* __restrict__ dst, int* __restrict__ cur, int* __restrict__ eid)
{
    const int e = blockIdx.x * 256 + threadIdx.x;
    const int p = atomicAdd(&cur[dst[e]], 1);
    eid[p] = e;
}

// =============================================================================
// Edge gather (no atomics): warp per node d:
//   aggH[d] = sum_{e in csr[d]} relu(U[src[e]] + V[d]);  deg[d] = cnt[d]
// =============================================================================
__global__ __launch_bounds__(256) void gather_kernel(
    const float* __restrict__ U, const float* __restrict__ V,
    const int* __restrict__ src, const int* __restrict__ eid,
    const int* __restrict__ csr, const int* __restrict__ cnt,
    float* __restrict__ aggH, float* __restrict__ deg)
{
    const int d = blockIdx.x * 8 + (threadIdx.x >> 5);
    const int l = threadIdx.x & 31;
    const int start = csr[d];
    const int n = cnt[d];

    const float4* v4 = (const float4*)(V + (size_t)d * 256);
    const float4 v0 = v4[l], v1 = v4[l + 32];
    float4 a0 = make_float4(0.f, 0.f, 0.f, 0.f);
    float4 a1 = make_float4(0.f, 0.f, 0.f, 0.f);

    const int nw = n < 32 ? n : 32;
    int myS = 0;
    if (l < nw) myS = src[eid[start + l]];
    for (int i = 0; i < nw; i++) {
        const int s = __shfl_sync(0xffffffffu, myS, i);
        const float4* u4 = (const float4*)(U + (size_t)s * 256);
        const float4 u0 = u4[l], u1 = u4[l + 32];
        a0.x += fmaxf(u0.x + v0.x, 0.f); a0.y += fmaxf(u0.y + v0.y, 0.f);
        a0.z += fmaxf(u0.z + v0.z, 0.f); a0.w += fmaxf(u0.w + v0.w, 0.f);
        a1.x += fmaxf(u1.x + v1.x, 0.f); a1.y += fmaxf(u1.y + v1.y, 0.f);
        a1.z += fmaxf(u1.z + v1.z, 0.f); a1.w += fmaxf(u1.w + v1.w, 0.f);
    }
    for (int i = 32; i < n; i++) {   // rare tail (deg > 32)
        const int s = src[eid[start + i]];
        const float4* u4 = (const float4*)(U + (size_t)s * 256);
        const float4 u0 = u4[l], u1 = u4[l + 32];
        a0.x += fmaxf(u0.x + v0.x, 0.f); a0.y += fmaxf(u0.y + v0.y, 0.f);
        a0.z += fmaxf(u0.z + v0.z, 0.f); a0.w += fmaxf(u0.w + v0.w, 0.f);
        a1.x += fmaxf(u1.x + v1.x, 0.f); a1.y += fmaxf(u1.y + v1.y, 0.f);
        a1.z += fmaxf(u1.z + v1.z, 0.f); a1.w += fmaxf(u1.w + v1.w, 0.f);
    }
    float4* o4 = (float4*)(aggH + (size_t)d * 256);
    o4[l] = a0;
    o4[l + 32] = a1;
    if (l == 0) deg[d] = (float)n;
}

// =============================================================================
// Readout second layer: logits[N,8] = r1[N,256] @ wr2[8,256]^T + br2
// =============================================================================
__global__ __launch_bounds__(256) void logits_kernel(
    const float* __restrict__ r1, const float* __restrict__ wr2,
    const float* __restrict__ br2, float* __restrict__ out)
{
    __shared__ float sw[8 * 257];
    const int tid = threadIdx.x;
    for (int i = tid; i < 2048; i += 256)
        sw[(i >> 8) * 257 + (i & 255)] = wr2[i];
    __syncthreads();

    const int row = blockIdx.x * 32 + (tid >> 3);
    const int o = tid & 7;
    const float* a = r1 + (size_t)row * 256;
    const float* w = sw + o * 257;
    float acc = 0.f;
#pragma unroll 8
    for (int k = 0; k < 256; k++) acc = fmaf(a[k], w[k], acc);
    out[(size_t)row * 8 + o] = acc + br2[o];
}

// =============================================================================
// Launcher
// =============================================================================
extern "C" void kernel_launch(void* const* d_in, const int* in_sizes, int n_in,
                              void* d_out, int out_size)
{
    const float* obs  = (const float*)d_in[0];
    const float* h0   = (const float*)d_in[1];
    const float* c0   = (const float*)d_in[2];
    const int*   src  = (const int*)d_in[3];
    const int*   dst  = (const int*)d_in[4];
    const float* w1a  = (const float*)d_in[5];
    const float* b1a  = (const float*)d_in[6];
    const float* w1b  = (const float*)d_in[7];
    const float* b1b  = (const float*)d_in[8];
    const float* w_ih = (const float*)d_in[9];
    const float* b_ih = (const float*)d_in[10];
    const float* w_hh = (const float*)d_in[11];
    const float* b_hh = (const float*)d_in[12];
    const float* w1   = (const float*)d_in[13];
    const float* b1   = (const float*)d_in[14];
    const float* we   = (const float*)d_in[15];
    const float* be   = (const float*)d_in[16];
    const float* we2  = (const float*)d_in[17];
    const float* be2  = (const float*)d_in[18];
    const float* wn   = (const float*)d_in[19];
    const float* bn   = (const float*)d_in[20];
    const float* wn2  = (const float*)d_in[21];
    const float* bn2  = (const float*)d_in[22];
    const float* wr   = (const float*)d_in[23];
    const float* br   = (const float*)d_in[24];
    const float* wr2  = (const float*)d_in[25];
    const float* br2  = (const float*)d_in[26];

    float* out    = (float*)d_out;
    float* logits = out;                       // [N, 8]
    float* h1     = out + (size_t)NN * 8;      // [N, 256]
    float* c1     = h1 + (size_t)NN * 256;     // [N, 256]

    float *p_t1, *p_x, *p_gates, *p_nf, *p_U, *p_V, *p_aggH, *p_deg, *p_aggE,
          *p_nh, *p_nf2, *p_r1;
    int *p_cnt, *p_csr, *p_cur, *p_eid, *p_bsum;
    cudaGetSymbolAddress((void**)&p_t1, g_t1);
    cudaGetSymbolAddress((void**)&p_x, g_x);
    cudaGetSymbolAddress((void**)&p_gates, g_gates);
    cudaGetSymbolAddress((void**)&p_nf, g_nf);
    cudaGetSymbolAddress((void**)&p_U, g_U);
    cudaGetSymbolAddress((void**)&p_V, g_V);
    cudaGetSymbolAddress((void**)&p_aggH, g_aggH);
    cudaGetSymbolAddress((void**)&p_deg, g_deg);
    cudaGetSymbolAddress((void**)&p_aggE, g_aggE);
    cudaGetSymbolAddress((void**)&p_nh, g_nh);
    cudaGetSymbolAddress((void**)&p_nf2, g_nf2);
    cudaGetSymbolAddress((void**)&p_r1, g_r1);
    cudaGetSymbolAddress((void**)&p_cnt, g_cnt);
    cudaGetSymbolAddress((void**)&p_csr, g_csr);
    cudaGetSymbolAddress((void**)&p_cur, g_cur);
    cudaGetSymbolAddress((void**)&p_eid, g_eid);
    cudaGetSymbolAddress((void**)&p_bsum, g_bsum);

    const dim3 blk(256);
    const int MT = NN / 128;   // 512 row tiles

    // ---- CSR build (independent of GEMM chain; runs early in the stream) ----
    zero_int_kernel<<<NN / 256, blk>>>(p_cnt);
    hist_kernel<<<EE / 256, blk>>>(dst, p_cnt);
    scan1_kernel<<<256, blk>>>(p_cnt, p_csr, p_bsum);
    scan2_kernel<<<1, blk>>>(p_bsum);
    scan3_kernel<<<256, blk>>>(p_csr, p_bsum, p_cur);
    scatter_id_kernel<<<EE / 256, blk>>>(dst, p_cur, p_eid);

    // 1. t1 = relu(obs @ w1a^T + b1a)                        [N,512] K=256
    tgemm<0, 1, 0, 0><<<dim3(8, MT), blk>>>(obs, nullptr, 256, w1a, nullptr, 256, 256,
                                            b1a, nullptr, nullptr, p_t1, 512);
    // 2. x = t1 @ w1b^T + b1b                                [N,256] K=512
    tgemm<0, 0, 0, 0><<<dim3(4, MT), blk>>>(p_t1, nullptr, 512, w1b, nullptr, 512, 512,
                                            b1b, nullptr, nullptr, p_x, 256);
    // 3. gates = x@w_ih^T + h0@w_hh^T + b_ih + b_hh          [N,1024]
    tgemm<0, 0, 0, 1><<<dim3(16, MT), blk>>>(p_x, h0, 256, w_ih, w_hh, 256, 256,
                                             b_ih, b_hh, nullptr, p_gates, 1024);
    // 4. LSTM pointwise -> h1, c1 (into output buffer)
    lstm_kernel<<<NN, blk>>>(p_gates, c0, h1, c1);
    // 5. nf = relu(h1) @ w1^T + b1                           [N,128] K=256
    tgemm<1, 0, 0, 0><<<dim3(2, MT), blk>>>(h1, nullptr, 256, w1, nullptr, 256, 256,
                                            b1, nullptr, nullptr, p_nf, 128);
    // 6a. U = nf @ weL^T + be                                [N,256] K=128
    tgemm<0, 0, 0, 0><<<dim3(4, MT), blk>>>(p_nf, nullptr, 128, we, nullptr, 256, 128,
                                            be, nullptr, nullptr, p_U, 256);
    // 6b. V = nf @ weR^T                                     [N,256] K=128
    tgemm<0, 0, 0, 0><<<dim3(4, MT), blk>>>(p_nf, nullptr, 128, we + 128, nullptr, 256, 128,
                                            nullptr, nullptr, nullptr, p_V, 256);
    // 7. gather: aggH[d] = sum relu(U[src]+V[d]); deg[d]=cnt[d]
    gather_kernel<<<NN / 8, blk>>>(p_U, p_V, src, p_eid, p_csr, p_cnt, p_aggH, p_deg);
    // 8. aggE = aggH @ we2^T + deg*be2                       [N,128] K=256
    tgemm<0, 0, 1, 0><<<dim3(2, MT), blk>>>(p_aggH, nullptr, 256, we2, nullptr, 256, 256,
                                            be2, nullptr, p_deg, p_aggE, 128);
    // 9. nh = relu(nf@wnL^T + aggE@wnR^T + bn)               [N,256]
    tgemm<0, 1, 0, 1><<<dim3(4, MT), blk>>>(p_nf, p_aggE, 128, wn, wn + 128, 256, 128,
                                            bn, nullptr, nullptr, p_nh, 256);
    // 10. nf2 = nh @ wn2^T + bn2                             [N,128] K=256
    tgemm<0, 0, 0, 0><<<dim3(2, MT), blk>>>(p_nh, nullptr, 256, wn2, nullptr, 256, 256,
                                            bn2, nullptr, nullptr, p_nf2, 128);
    // 11. r1 = relu(nf2 @ wr^T + br)                         [N,256] K=128
    tgemm<0, 1, 0, 0><<<dim3(4, MT), blk>>>(p_nf2, nullptr, 128, wr, nullptr, 128, 128,
                                            br, nullptr, nullptr, p_r1, 256);
    // 12. logits = r1 @ wr2^T + br2                          [N,8]
    logits_kernel<<<NN / 32, blk>>>(p_r1, wr2, br2, logits);
}

// round 8
// speedup vs baseline: 5.1892x; 1.6230x over previous
#include <cuda_runtime.h>
#include <cuda_bf16.h>
#include <math.h>
#include <stdint.h>

#define NN 65536
#define EE 524288
// dims: OBS=256 HID=512 MID=256 LSTM=256 DOUT=128 DLAST=128 RFM=256 LH=256 ACT=8

typedef __nv_bfloat16 bf16;

// ---------------- scratch (device globals; no allocation allowed) -------------
// activation planes (hi/lo bf16)
__device__ __align__(16) bf16 g_obsH[NN * 256], g_obsL[NN * 256];
__device__ __align__(16) bf16 g_h0H[NN * 256],  g_h0L[NN * 256];
__device__ __align__(16) bf16 g_t1H[NN * 512],  g_t1L[NN * 512];
__device__ __align__(16) bf16 g_xH[NN * 256],   g_xL[NN * 256];
__device__ __align__(16) bf16 g_gH[NN * 1024],  g_gL[NN * 1024];
__device__ __align__(16) bf16 g_rhH[NN * 256],  g_rhL[NN * 256];
__device__ __align__(16) bf16 g_nfH[NN * 128],  g_nfL[NN * 128];
__device__ __align__(16) bf16 g_UH[NN * 256],   g_UL[NN * 256];
__device__ __align__(16) bf16 g_VH[NN * 256],   g_VL[NN * 256];
__device__ __align__(16) bf16 g_aHH[NN * 256],  g_aHL[NN * 256];
__device__ __align__(16) bf16 g_aEH[NN * 128],  g_aEL[NN * 128];
__device__ __align__(16) bf16 g_nhH[NN * 256],  g_nhL[NN * 256];
__device__ __align__(16) bf16 g_n2H[NN * 128],  g_n2L[NN * 128];
__device__ __align__(16) bf16 g_r1H[NN * 256],  g_r1L[NN * 256];
// weight planes
__device__ __align__(16) bf16 g_w1aH[512 * 256],  g_w1aL[512 * 256];
__device__ __align__(16) bf16 g_w1bH[256 * 512],  g_w1bL[256 * 512];
__device__ __align__(16) bf16 g_wihH[1024 * 256], g_wihL[1024 * 256];
__device__ __align__(16) bf16 g_whhH[1024 * 256], g_whhL[1024 * 256];
__device__ __align__(16) bf16 g_w1H[128 * 256],   g_w1L[128 * 256];
__device__ __align__(16) bf16 g_weH[256 * 256],   g_weL[256 * 256];
__device__ __align__(16) bf16 g_we2H[128 * 256],  g_we2L[128 * 256];
__device__ __align__(16) bf16 g_wnH[256 * 256],   g_wnL[256 * 256];
__device__ __align__(16) bf16 g_wn2H[128 * 256],  g_wn2L[128 * 256];
__device__ __align__(16) bf16 g_wrH[256 * 128],   g_wrL[256 * 128];
// misc
__device__ float g_deg[NN];
__device__ int g_cnt[NN];
__device__ int g_csr[NN];
__device__ int g_cur[NN];
__device__ int g_eid[EE];
__device__ int g_bsum[256];

// ---------------------------- helpers -----------------------------------------
__device__ __forceinline__ uint32_t sm2u(const void* p) {
    return (uint32_t)__cvta_generic_to_shared(p);
}
__device__ __forceinline__ uint32_t pk(bf16 a, bf16 b) {
    return (uint32_t)__bfloat16_as_ushort(a) |
           ((uint32_t)__bfloat16_as_ushort(b) << 16);
}
__device__ __forceinline__ void split2(float a, float b, uint32_t& hi, uint32_t& lo) {
    const bf16 ha = __float2bfloat16_rn(a), hb = __float2bfloat16_rn(b);
    hi = pk(ha, hb);
    lo = pk(__float2bfloat16_rn(a - __bfloat162float(ha)),
            __float2bfloat16_rn(b - __bfloat162float(hb)));
}
__device__ __forceinline__ void mma16(float* d, const uint32_t* a, const uint32_t* b) {
    asm volatile(
        "mma.sync.aligned.m16n8k16.row.col.f32.bf16.bf16.f32 "
        "{%0,%1,%2,%3}, {%4,%5,%6,%7}, {%8,%9}, {%0,%1,%2,%3};"
        : "+f"(d[0]), "+f"(d[1]), "+f"(d[2]), "+f"(d[3])
        : "r"(a[0]), "r"(a[1]), "r"(a[2]), "r"(a[3]), "r"(b[0]), "r"(b[1]));
}
__device__ __forceinline__ void ldsm4(uint32_t* r, uint32_t addr) {
    asm volatile(
        "ldmatrix.sync.aligned.m8n8.x4.shared.b16 {%0,%1,%2,%3}, [%4];"
        : "=r"(r[0]), "=r"(r[1]), "=r"(r[2]), "=r"(r[3]) : "r"(addr));
}
__device__ __forceinline__ void cpa16(uint32_t s, const void* g) {
    asm volatile("cp.async.cg.shared.global [%0], [%1], 16;" :: "r"(s), "l"(g));
}
__device__ __forceinline__ void cpcommit() {
    asm volatile("cp.async.commit_group;" ::: "memory");
}
template <int N>
__device__ __forceinline__ void cpwait() {
    asm volatile("cp.async.wait_group %0;" :: "n"(N) : "memory");
}

// =============================================================================
// BF16x3 mma.sync GEMM, planes in / planes out.
// C = act(A@W^T [+ A2@W2^T] + bias [+bias2]); A,W given as bf16 hi/lo planes.
// BM=128, BN=128, BK=32; 256 threads = 8 warps (4m x 2n); warp tile 32x64.
// cp.async double-buffered (2 x 40KB stages); smem pitch 40 bf16 (80B).
// DEGBIAS: v = acc + deg[row]*bias[col]. Requires M%128, Nc%128, K%32 == 0.
// =============================================================================
#define AP 40
#define STG_ELT 20480              // elements per stage (40960 B)
#define TG_SMEM (2 * STG_ELT * 2)  // bytes

__device__ __forceinline__ void tg_issue(
    const bf16* pAh, const bf16* pAl, int ldA, int rowBase,
    const bf16* pWh, const bf16* pWl, int ldW, int colBase,
    int kk0, bf16* sb, int tid)
{
#pragma unroll
    for (int i = 0; i < 2; i++) {
        const int idx = tid + 256 * i;
        const int r = idx >> 2, c8 = (idx & 3) * 8;
        const int so = r * AP + c8;
        cpa16(sm2u(sb + so),        pAh + (size_t)(rowBase + r) * ldA + kk0 + c8);
        cpa16(sm2u(sb + 5120 + so), pAl + (size_t)(rowBase + r) * ldA + kk0 + c8);
        cpa16(sm2u(sb + 10240 + so), pWh + (size_t)(colBase + r) * ldW + kk0 + c8);
        cpa16(sm2u(sb + 15360 + so), pWl + (size_t)(colBase + r) * ldW + kk0 + c8);
    }
    cpcommit();
}

template <int RELU_OUT, int DEGBIAS, int DUAL>
__global__ __launch_bounds__(256) void tg(
    const bf16* __restrict__ Ah_, const bf16* __restrict__ Al_,
    const bf16* __restrict__ A2h, const bf16* __restrict__ A2l, int ldA,
    const bf16* __restrict__ Wh_, const bf16* __restrict__ Wl_,
    const bf16* __restrict__ W2h, const bf16* __restrict__ W2l, int ldW, int K,
    const float* __restrict__ bias, const float* __restrict__ bias2,
    const float* __restrict__ deg,
    bf16* __restrict__ Ch, bf16* __restrict__ Cl, int ldC)
{
    extern __shared__ bf16 sm[];
    const int tid = threadIdx.x, warp = tid >> 5, lane = tid & 31;
    const int wy = warp >> 1, wx = warp & 1;
    const int g = lane >> 2, tg2 = lane & 3;
    const int rowBase = blockIdx.y * 128, colBase = blockIdx.x * 128;

    float acc[2][4][2][4];
#pragma unroll
    for (int a = 0; a < 2; a++)
#pragma unroll
        for (int b = 0; b < 4; b++)
#pragma unroll
            for (int c = 0; c < 2; c++)
#pragma unroll
                for (int d = 0; d < 4; d++) acc[a][b][c][d] = 0.f;

    const int ncp = K >> 5, total = DUAL ? 2 * ncp : ncp;

    // prologue: stage chunk 0
    tg_issue(Ah_, Al_, ldA, rowBase, Wh_, Wl_, ldW, colBase, 0, sm, tid);

#pragma unroll 1
    for (int c = 0; c < total; c++) {
        if (c + 1 < total) {
            const int n = c + 1;
            const int ph = DUAL ? (n >= ncp) : 0;
            tg_issue(ph ? A2h : Ah_, ph ? A2l : Al_, ldA, rowBase,
                     ph ? W2h : Wh_, ph ? W2l : Wl_, ldW, colBase,
                     (ph ? n - ncp : n) << 5, sm + (n & 1) * STG_ELT, tid);
            cpwait<1>();
        } else {
            cpwait<0>();
        }
        __syncthreads();

        const uint32_t base = sm2u(sm) + (uint32_t)(c & 1) * (STG_ELT * 2);
#pragma unroll
        for (int kk = 0; kk < 32; kk += 16) {
            uint32_t ah[2][4], al[2][4], bh[4][4], bl[4][4];
#pragma unroll
            for (int mt = 0; mt < 2; mt++) {
                const uint32_t off =
                    (uint32_t)((wy * 32 + mt * 16 + (lane & 15)) * AP +
                               kk + ((lane >> 4) << 3)) * 2;
                ldsm4(ah[mt], base + off);
                ldsm4(al[mt], base + 10240 + off);
            }
#pragma unroll
            for (int nb = 0; nb < 4; nb++) {
                const uint32_t off =
                    (uint32_t)((wx * 64 + nb * 16 + (lane & 7) +
                                (((lane >> 4) & 1) << 3)) * AP +
                               kk + (((lane >> 3) & 1) << 3)) * 2;
                ldsm4(bh[nb], base + 20480 + off);
                ldsm4(bl[nb], base + 30720 + off);
            }
#pragma unroll
            for (int mt = 0; mt < 2; mt++)
#pragma unroll
                for (int nb = 0; nb < 4; nb++)
#pragma unroll
                    for (int h = 0; h < 2; h++) {
                        mma16(acc[mt][nb][h], ah[mt], &bh[nb][2 * h]);
                        mma16(acc[mt][nb][h], ah[mt], &bl[nb][2 * h]);
                        mma16(acc[mt][nb][h], al[mt], &bh[nb][2 * h]);
                    }
        }
        __syncthreads();
    }

    // epilogue: bias (+deg scale), relu, split into hi/lo planes
#pragma unroll
    for (int mt = 0; mt < 2; mt++) {
        const int row = rowBase + wy * 32 + mt * 16 + g;
        const float d0 = DEGBIAS ? deg[row] : 1.f;
        const float d1 = DEGBIAS ? deg[row + 8] : 1.f;
#pragma unroll
        for (int nb = 0; nb < 4; nb++)
#pragma unroll
            for (int h = 0; h < 2; h++) {
                const int col = colBase + wx * 64 + nb * 16 + h * 8 + 2 * tg2;
                float bb0 = 0.f, bb1 = 0.f;
                if (bias)  { bb0 = bias[col];  bb1 = bias[col + 1]; }
                if (DUAL && bias2) { bb0 += bias2[col]; bb1 += bias2[col + 1]; }
                float v0 = acc[mt][nb][h][0] + d0 * bb0;
                float v1 = acc[mt][nb][h][1] + d0 * bb1;
                float v2 = acc[mt][nb][h][2] + d1 * bb0;
                float v3 = acc[mt][nb][h][3] + d1 * bb1;
                if (RELU_OUT) {
                    v0 = fmaxf(v0, 0.f); v1 = fmaxf(v1, 0.f);
                    v2 = fmaxf(v2, 0.f); v3 = fmaxf(v3, 0.f);
                }
                uint32_t hi, lo;
                split2(v0, v1, hi, lo);
                *(uint32_t*)&Ch[(size_t)row * ldC + col] = hi;
                *(uint32_t*)&Cl[(size_t)row * ldC + col] = lo;
                split2(v2, v3, hi, lo);
                *(uint32_t*)&Ch[(size_t)(row + 8) * ldC + col] = hi;
                *(uint32_t*)&Cl[(size_t)(row + 8) * ldC + col] = lo;
            }
    }
}

// =============================================================================
// fp32 -> bf16 hi/lo plane split (weights, obs, h0). grid = n/1024, 256 thr.
// =============================================================================
__global__ __launch_bounds__(256) void split_kernel(
    const float4* __restrict__ in, uint2* __restrict__ hi, uint2* __restrict__ lo)
{
    const int idx = blockIdx.x * 256 + threadIdx.x;
    const float4 v = in[idx];
    uint32_t h0, l0, h1, l1;
    split2(v.x, v.y, h0, l0);
    split2(v.z, v.w, h1, l1);
    hi[idx] = make_uint2(h0, h1);
    lo[idx] = make_uint2(l0, l1);
}

// =============================================================================
// LSTM pointwise: gate planes + c0 -> h1, c1 (fp32 out) + relu(h1) planes
// =============================================================================
__device__ __forceinline__ float sigm(float x) {
    return __fdividef(1.f, 1.f + __expf(-x));
}
__device__ __forceinline__ float ftanh(float x) {
    const float e = __expf(2.f * x);
    return __fdividef(e - 1.f, e + 1.f);
}

__global__ __launch_bounds__(256) void lstm_kernel(
    const bf16* __restrict__ Gh, const bf16* __restrict__ Gl,
    const float* __restrict__ c0,
    float* __restrict__ h1, float* __restrict__ c1,
    bf16* __restrict__ rhh, bf16* __restrict__ rhl)
{
    const int idx = blockIdx.x * 256 + threadIdx.x;     // NN*128 total
    const int n = idx >> 7, jp = (idx & 127) << 1;
    const size_t base = (size_t)n * 1024 + jp;

    float2 gg[4];
#pragma unroll
    for (int q = 0; q < 4; q++) {
        const float2 h = __bfloat1622float2(*(const __nv_bfloat162*)&Gh[base + q * 256]);
        const float2 l = __bfloat1622float2(*(const __nv_bfloat162*)&Gl[base + q * 256]);
        gg[q] = make_float2(h.x + l.x, h.y + l.y);
    }
    const size_t o = (size_t)n * 256 + jp;
    const float2 cc0 = *(const float2*)&c0[o];

    const float i0 = sigm(gg[0].x), i1 = sigm(gg[0].y);
    const float f0 = sigm(gg[1].x), f1 = sigm(gg[1].y);
    const float t0 = ftanh(gg[2].x), t1 = ftanh(gg[2].y);
    const float o0 = sigm(gg[3].x), o1 = sigm(gg[3].y);
    const float c0v = f0 * cc0.x + i0 * t0;
    const float c1v = f1 * cc0.y + i1 * t1;
    const float h0v = o0 * ftanh(c0v);
    const float h1v = o1 * ftanh(c1v);

    *(float2*)&c1[o] = make_float2(c0v, c1v);
    *(float2*)&h1[o] = make_float2(h0v, h1v);
    uint32_t hi, lo;
    split2(fmaxf(h0v, 0.f), fmaxf(h1v, 0.f), hi, lo);
    *(uint32_t*)&rhh[o] = hi;
    *(uint32_t*)&rhl[o] = lo;
}

// =============================================================================
// CSR build: histogram -> 2-level exclusive scan -> id scatter
// =============================================================================
__global__ __launch_bounds__(256) void zero_int_kernel(int* __restrict__ p)
{
    p[blockIdx.x * 256 + threadIdx.x] = 0;
}
__global__ __launch_bounds__(256) void hist_kernel(const int* __restrict__ dst,
                                                   int* __restrict__ cnt)
{
    atomicAdd(&cnt[dst[blockIdx.x * 256 + threadIdx.x]], 1);
}
__global__ __launch_bounds__(256) void scan1_kernel(
    const int* __restrict__ cnt, int* __restrict__ csr, int* __restrict__ bsum)
{
    __shared__ int s[256];
    const int t = threadIdx.x, b = blockIdx.x;
    const int v = cnt[b * 256 + t];
    s[t] = v; __syncthreads();
#pragma unroll
    for (int off = 1; off < 256; off <<= 1) {
        int x = (t >= off) ? s[t - off] : 0;
        __syncthreads();
        s[t] += x;
        __syncthreads();
    }
    csr[b * 256 + t] = s[t] - v;
    if (t == 255) bsum[b] = s[255];
}
__global__ __launch_bounds__(256) void scan2_kernel(int* __restrict__ bsum)
{
    __shared__ int s[256];
    const int t = threadIdx.x;
    const int v = bsum[t];
    s[t] = v; __syncthreads();
#pragma unroll
    for (int off = 1; off < 256; off <<= 1) {
        int x = (t >= off) ? s[t - off] : 0;
        __syncthreads();
        s[t] += x;
        __syncthreads();
    }
    bsum[t] = s[t] - v;
}
__global__ __launch_bounds__(256) void scan3_kernel(
    int* __restrict__ csr, const int* __restrict__ bsum, int* __restrict__ cur)
{
    const int i = blockIdx.x * 256 + threadIdx.x;
    const int x = csr[i] + bsum[i >> 8];
    csr[i] = x;
    cur[i] = x;
}
__global__ __launch_bounds__(256) void scatter_id_kernel(
    const int* __restrict__ dst, int* __restrict__ cur, int* __restrict__ eid)
{
    const int e = blockIdx.x * 256 + threadIdx.x;
    const int p = atomicAdd(&cur[dst[e]], 1);
    eid[p] = e;
}

// =============================================================================
// Edge gather (planes): warp per node d:
//   aggH[d] = sum_{e in csr[d]} relu(U[src[e]] + V[d]);  deg[d] = cnt[d]
// =============================================================================
__device__ __forceinline__ void unpack8(uint4 h, uint4 l, float* o) {
    const __nv_bfloat162* hp = (const __nv_bfloat162*)&h;
    const __nv_bfloat162* lp = (const __nv_bfloat162*)&l;
#pragma unroll
    for (int j = 0; j < 4; j++) {
        const float2 fh = __bfloat1622float2(hp[j]);
        const float2 fl = __bfloat1622float2(lp[j]);
        o[2 * j] = fh.x + fl.x;
        o[2 * j + 1] = fh.y + fl.y;
    }
}

__global__ __launch_bounds__(256) void gather_kernel(
    const bf16* __restrict__ Uh, const bf16* __restrict__ Ul,
    const bf16* __restrict__ Vh, const bf16* __restrict__ Vl,
    const int* __restrict__ src, const int* __restrict__ eid,
    const int* __restrict__ csr, const int* __restrict__ cnt,
    bf16* __restrict__ aggHh, bf16* __restrict__ aggHl, float* __restrict__ deg)
{
    const int d = blockIdx.x * 8 + (threadIdx.x >> 5);
    const int l = threadIdx.x & 31;
    const int start = csr[d];
    const int n = cnt[d];

    float v[8];
    unpack8(((const uint4*)(Vh + (size_t)d * 256))[l],
            ((const uint4*)(Vl + (size_t)d * 256))[l], v);
    float a[8];
#pragma unroll
    for (int j = 0; j < 8; j++) a[j] = 0.f;

    const int nw = n < 32 ? n : 32;
    int myS = 0;
    if (l < nw) myS = src[eid[start + l]];
    for (int i = 0; i < nw; i++) {
        const int s = __shfl_sync(0xffffffffu, myS, i);
        float u[8];
        unpack8(((const uint4*)(Uh + (size_t)s * 256))[l],
                ((const uint4*)(Ul + (size_t)s * 256))[l], u);
#pragma unroll
        for (int j = 0; j < 8; j++) a[j] += fmaxf(u[j] + v[j], 0.f);
    }
    for (int i = 32; i < n; i++) {       // rare tail (deg > 32)
        const int s = src[eid[start + i]];
        float u[8];
        unpack8(((const uint4*)(Uh + (size_t)s * 256))[l],
                ((const uint4*)(Ul + (size_t)s * 256))[l], u);
#pragma unroll
        for (int j = 0; j < 8; j++) a[j] += fmaxf(u[j] + v[j], 0.f);
    }

    uint4 oh, ol;
    split2(a[0], a[1], oh.x, ol.x);
    split2(a[2], a[3], oh.y, ol.y);
    split2(a[4], a[5], oh.z, ol.z);
    split2(a[6], a[7], oh.w, ol.w);
    ((uint4*)(aggHh + (size_t)d * 256))[l] = oh;
    ((uint4*)(aggHl + (size_t)d * 256))[l] = ol;
    if (l == 0) deg[d] = (float)n;
}

// =============================================================================
// Readout second layer: logits[N,8] = (r1h+r1l)[N,256] @ wr2[8,256]^T + br2
// =============================================================================
__global__ __launch_bounds__(256) void logits_kernel(
    const bf16* __restrict__ r1h, const bf16* __restrict__ r1l,
    const float* __restrict__ wr2, const float* __restrict__ br2,
    float* __restrict__ out)
{
    __shared__ float sw[8 * 257];
    const int tid = threadIdx.x;
    for (int i = tid; i < 2048; i += 256)
        sw[(i >> 8) * 257 + (i & 255)] = wr2[i];
    __syncthreads();

    const int row = blockIdx.x * 32 + (tid >> 3);
    const int o = tid & 7;
    const __nv_bfloat162* ah = (const __nv_bfloat162*)(r1h + (size_t)row * 256);
    const __nv_bfloat162* al = (const __nv_bfloat162*)(r1l + (size_t)row * 256);
    const float* w = sw + o * 257;
    float acc = 0.f;
#pragma unroll 8
    for (int k = 0; k < 128; k++) {
        const float2 h = __bfloat1622float2(ah[k]);
        const float2 l = __bfloat1622float2(al[k]);
        acc = fmaf(h.x + l.x, w[2 * k], acc);
        acc = fmaf(h.y + l.y, w[2 * k + 1], acc);
    }
    out[(size_t)row * 8 + o] = acc + br2[o];
}

// =============================================================================
// Launcher
// =============================================================================
#define GSYM(var, sym) cudaGetSymbolAddress((void**)&var, sym)

extern "C" void kernel_launch(void* const* d_in, const int* in_sizes, int n_in,
                              void* d_out, int out_size)
{
    const float* obs  = (const float*)d_in[0];
    const float* h0   = (const float*)d_in[1];
    const float* c0   = (const float*)d_in[2];
    const int*   src  = (const int*)d_in[3];
    const int*   dst  = (const int*)d_in[4];
    const float* w1a  = (const float*)d_in[5];
    const float* b1a  = (const float*)d_in[6];
    const float* w1b  = (const float*)d_in[7];
    const float* b1b  = (const float*)d_in[8];
    const float* w_ih = (const float*)d_in[9];
    const float* b_ih = (const float*)d_in[10];
    const float* w_hh = (const float*)d_in[11];
    const float* b_hh = (const float*)d_in[12];
    const float* w1   = (const float*)d_in[13];
    const float* b1   = (const float*)d_in[14];
    const float* we   = (const float*)d_in[15];
    const float* be   = (const float*)d_in[16];
    const float* we2  = (const float*)d_in[17];
    const float* be2  = (const float*)d_in[18];
    const float* wn   = (const float*)d_in[19];
    const float* bn   = (const float*)d_in[20];
    const float* wn2  = (const float*)d_in[21];
    const float* bn2  = (const float*)d_in[22];
    const float* wr   = (const float*)d_in[23];
    const float* br   = (const float*)d_in[24];
    const float* wr2  = (const float*)d_in[25];
    const float* br2  = (const float*)d_in[26];

    float* out    = (float*)d_out;
    float* logits = out;                       // [N, 8]
    float* h1     = out + (size_t)NN * 8;      // [N, 256]
    float* c1     = h1 + (size_t)NN * 256;     // [N, 256]

    bf16 *obsH, *obsL, *h0H, *h0L, *t1H, *t1L, *xH, *xL, *gH, *gL, *rhH, *rhL,
         *nfH, *nfL, *UH, *UL, *VH, *VL, *aHH, *aHL, *aEH, *aEL, *nhH, *nhL,
         *n2H, *n2L, *r1H, *r1L;
    bf16 *w1aH, *w1aL, *w1bH, *w1bL, *wihH, *wihL, *whhH, *whhL, *w1H, *w1L,
         *weH, *weL, *we2H, *we2L, *wnH, *wnL, *wn2H, *wn2L, *wrH, *wrL;
    float *p_deg;
    int *p_cnt, *p_csr, *p_cur, *p_eid, *p_bsum;

    GSYM(obsH, g_obsH); GSYM(obsL, g_obsL); GSYM(h0H, g_h0H); GSYM(h0L, g_h0L);
    GSYM(t1H, g_t1H);   GSYM(t1L, g_t1L);   GSYM(xH, g_xH);   GSYM(xL, g_xL);
    GSYM(gH, g_gH);     GSYM(gL, g_gL);     GSYM(rhH, g_rhH); GSYM(rhL, g_rhL);
    GSYM(nfH, g_nfH);   GSYM(nfL, g_nfL);   GSYM(UH, g_UH);   GSYM(UL, g_UL);
    GSYM(VH, g_VH);     GSYM(VL, g_VL);     GSYM(aHH, g_aHH); GSYM(aHL, g_aHL);
    GSYM(aEH, g_aEH);   GSYM(aEL, g_aEL);   GSYM(nhH, g_nhH); GSYM(nhL, g_nhL);
    GSYM(n2H, g_n2H);   GSYM(n2L, g_n2L);   GSYM(r1H, g_r1H); GSYM(r1L, g_r1L);
    GSYM(w1aH, g_w1aH); GSYM(w1aL, g_w1aL); GSYM(w1bH, g_w1bH); GSYM(w1bL, g_w1bL);
    GSYM(wihH, g_wihH); GSYM(wihL, g_wihL); GSYM(whhH, g_whhH); GSYM(whhL, g_whhL);
    GSYM(w1H, g_w1H);   GSYM(w1L, g_w1L);   GSYM(weH, g_weH);   GSYM(weL, g_weL);
    GSYM(we2H, g_we2H); GSYM(we2L, g_we2L); GSYM(wnH, g_wnH);   GSYM(wnL, g_wnL);
    GSYM(wn2H, g_wn2H); GSYM(wn2L, g_wn2L); GSYM(wrH, g_wrH);   GSYM(wrL, g_wrL);
    GSYM(p_deg, g_deg);
    GSYM(p_cnt, g_cnt); GSYM(p_csr, g_csr); GSYM(p_cur, g_cur);
    GSYM(p_eid, g_eid); GSYM(p_bsum, g_bsum);

    cudaFuncSetAttribute(tg<1,0,0>, cudaFuncAttributeMaxDynamicSharedMemorySize, TG_SMEM);
    cudaFuncSetAttribute(tg<0,0,0>, cudaFuncAttributeMaxDynamicSharedMemorySize, TG_SMEM);
    cudaFuncSetAttribute(tg<0,0,1>, cudaFuncAttributeMaxDynamicSharedMemorySize, TG_SMEM);
    cudaFuncSetAttribute(tg<0,1,0>, cudaFuncAttributeMaxDynamicSharedMemorySize, TG_SMEM);
    cudaFuncSetAttribute(tg<1,0,1>, cudaFuncAttributeMaxDynamicSharedMemorySize, TG_SMEM);

    const dim3 blk(256);
    const int MT = NN / 128;   // 512 row tiles

    // ---- plane splits (weights + external activations) ----
    split_kernel<<<NN * 256 / 1024, blk>>>((const float4*)obs, (uint2*)obsH, (uint2*)obsL);
    split_kernel<<<NN * 256 / 1024, blk>>>((const float4*)h0, (uint2*)h0H, (uint2*)h0L);
    split_kernel<<<512 * 256 / 1024, blk>>>((const float4*)w1a, (uint2*)w1aH, (uint2*)w1aL);
    split_kernel<<<256 * 512 / 1024, blk>>>((const float4*)w1b, (uint2*)w1bH, (uint2*)w1bL);
    split_kernel<<<1024 * 256 / 1024, blk>>>((const float4*)w_ih, (uint2*)wihH, (uint2*)wihL);
    split_kernel<<<1024 * 256 / 1024, blk>>>((const float4*)w_hh, (uint2*)whhH, (uint2*)whhL);
    split_kernel<<<128 * 256 / 1024, blk>>>((const float4*)w1, (uint2*)w1H, (uint2*)w1L);
    split_kernel<<<256 * 256 / 1024, blk>>>((const float4*)we, (uint2*)weH, (uint2*)weL);
    split_kernel<<<128 * 256 / 1024, blk>>>((const float4*)we2, (uint2*)we2H, (uint2*)we2L);
    split_kernel<<<256 * 256 / 1024, blk>>>((const float4*)wn, (uint2*)wnH, (uint2*)wnL);
    split_kernel<<<128 * 256 / 1024, blk>>>((const float4*)wn2, (uint2*)wn2H, (uint2*)wn2L);
    split_kernel<<<256 * 128 / 1024, blk>>>((const float4*)wr, (uint2*)wrH, (uint2*)wrL);

    // ---- CSR build ----
    zero_int_kernel<<<NN / 256, blk>>>(p_cnt);
    hist_kernel<<<EE / 256, blk>>>(dst, p_cnt);
    scan1_kernel<<<256, blk>>>(p_cnt, p_csr, p_bsum);
    scan2_kernel<<<1, blk>>>(p_bsum);
    scan3_kernel<<<256, blk>>>(p_csr, p_bsum, p_cur);
    scatter_id_kernel<<<EE / 256, blk>>>(dst, p_cur, p_eid);

    // 1. t1 = relu(obs @ w1a^T + b1a)                        [N,512] K=256
    tg<1,0,0><<<dim3(4, MT), blk, TG_SMEM>>>(obsH, obsL, nullptr, nullptr, 256,
                                             w1aH, w1aL, nullptr, nullptr, 256, 256,
                                             b1a, nullptr, nullptr, t1H, t1L, 512);
    // 2. x = t1 @ w1b^T + b1b                                [N,256] K=512
    tg<0,0,0><<<dim3(2, MT), blk, TG_SMEM>>>(t1H, t1L, nullptr, nullptr, 512,
                                             w1bH, w1bL, nullptr, nullptr, 512, 512,
                                             b1b, nullptr, nullptr, xH, xL, 256);
    // 3. gates = x@w_ih^T + h0@w_hh^T + b_ih + b_hh          [N,1024]
    tg<0,0,1><<<dim3(8, MT), blk, TG_SMEM>>>(xH, xL, h0H, h0L, 256,
                                             wihH, wihL, whhH, whhL, 256, 256,
                                             b_ih, b_hh, nullptr, gH, gL, 1024);
    // 4. LSTM pointwise -> h1, c1 (fp32 out) + relu(h1) planes
    lstm_kernel<<<NN / 2, blk>>>(gH, gL, c0, h1, c1, rhH, rhL);
    // 5. nf = relu(h1) @ w1^T + b1                           [N,128] K=256
    tg<0,0,0><<<dim3(1, MT), blk, TG_SMEM>>>(rhH, rhL, nullptr, nullptr, 256,
                                             w1H, w1L, nullptr, nullptr, 256, 256,
                                             b1, nullptr, nullptr, nfH, nfL, 128);
    // 6a. U = nf @ weL^T + be                                [N,256] K=128
    tg<0,0,0><<<dim3(2, MT), blk, TG_SMEM>>>(nfH, nfL, nullptr, nullptr, 128,
                                             weH, weL, nullptr, nullptr, 256, 128,
                                             be, nullptr, nullptr, UH, UL, 256);
    // 6b. V = nf @ weR^T                                     [N,256] K=128
    tg<0,0,0><<<dim3(2, MT), blk, TG_SMEM>>>(nfH, nfL, nullptr, nullptr, 128,
                                             weH + 128, weL + 128, nullptr, nullptr, 256, 128,
                                             nullptr, nullptr, nullptr, VH, VL, 256);
    // 7. gather: aggH[d] = sum relu(U[src]+V[d]); deg[d]=cnt[d]
    gather_kernel<<<NN / 8, blk>>>(UH, UL, VH, VL, src, p_eid, p_csr, p_cnt,
                                   aHH, aHL, p_deg);
    // 8. aggE = aggH @ we2^T + deg*be2                       [N,128] K=256
    tg<0,1,0><<<dim3(1, MT), blk, TG_SMEM>>>(aHH, aHL, nullptr, nullptr, 256,
                                             we2H, we2L, nullptr, nullptr, 256, 256,
                                             be2, nullptr, p_deg, aEH, aEL, 128);
    // 9. nh = relu(nf@wnL^T + aggE@wnR^T + bn)               [N,256]
    tg<1,0,1><<<dim3(2, MT), blk, TG_SMEM>>>(nfH, nfL, aEH, aEL, 128,
                                             wnH, wnL, wnH + 128, wnL + 128, 256, 128,
                                             bn, nullptr, nullptr, nhH, nhL, 256);
    // 10. nf2 = nh @ wn2^T + bn2                             [N,128] K=256
    tg<0,0,0><<<dim3(1, MT), blk, TG_SMEM>>>(nhH, nhL, nullptr, nullptr, 256,
                                             wn2H, wn2L, nullptr, nullptr, 256, 256,
                                             bn2, nullptr, nullptr, n2H, n2L, 128);
    // 11. r1 = relu(nf2 @ wr^T + br)                         [N,256] K=128
    tg<1,0,0><<<dim3(2, MT), blk, TG_SMEM>>>(n2H, n2L, nullptr, nullptr, 128,
                                             wrH, wrL, nullptr, nullptr, 128, 128,
                                             br, nullptr, nullptr, r1H, r1L, 256);
    // 12. logits = r1 @ wr2^T + br2                          [N,8]
    logits_kernel<<<NN / 32, blk>>>(r1H, r1L, wr2, br2, logits);
}

// round 10
// speedup vs baseline: 5.8788x; 1.1329x over previous
#include <cuda_runtime.h>
#include <cuda_bf16.h>
#include <math.h>
#include <stdint.h>

#define NN 65536
#define EE 524288
// dims: OBS=256 HID=512 MID=256 LSTM=256 DOUT=128 DLAST=128 RFM=256 LH=256 ACT=8

typedef __nv_bfloat16 bf16;

// ---------------- scratch (device globals; no allocation allowed) -------------
__device__ __align__(16) bf16 g_obsH[NN * 256], g_obsL[NN * 256];
__device__ __align__(16) bf16 g_h0H[NN * 256],  g_h0L[NN * 256];
__device__ __align__(16) bf16 g_t1H[NN * 512],  g_t1L[NN * 512];
__device__ __align__(16) bf16 g_xH[NN * 256],   g_xL[NN * 256];
__device__ __align__(16) bf16 g_rhH[NN * 256],  g_rhL[NN * 256];
__device__ __align__(16) bf16 g_nfH[NN * 128],  g_nfL[NN * 128];
__device__ __align__(16) bf16 g_UH[NN * 256],   g_UL[NN * 256];
__device__ __align__(16) bf16 g_VH[NN * 256],   g_VL[NN * 256];
__device__ __align__(16) bf16 g_aHH[NN * 256],  g_aHL[NN * 256];
__device__ __align__(16) bf16 g_aEH[NN * 128],  g_aEL[NN * 128];
__device__ __align__(16) bf16 g_nhH[NN * 256],  g_nhL[NN * 256];
__device__ __align__(16) bf16 g_n2H[NN * 128],  g_n2L[NN * 128];
__device__ __align__(16) bf16 g_r1H[NN * 256],  g_r1L[NN * 256];
// weight planes (wih/whh stored gate-interleaved: row' = unit*4 + gate)
__device__ __align__(16) bf16 g_w1aH[512 * 256],  g_w1aL[512 * 256];
__device__ __align__(16) bf16 g_w1bH[256 * 512],  g_w1bL[256 * 512];
__device__ __align__(16) bf16 g_wihH[1024 * 256], g_wihL[1024 * 256];
__device__ __align__(16) bf16 g_whhH[1024 * 256], g_whhL[1024 * 256];
__device__ __align__(16) bf16 g_w1H[128 * 256],   g_w1L[128 * 256];
__device__ __align__(16) bf16 g_weH[256 * 256],   g_weL[256 * 256];
__device__ __align__(16) bf16 g_we2H[128 * 256],  g_we2L[128 * 256];
__device__ __align__(16) bf16 g_wnH[256 * 256],   g_wnL[256 * 256];
__device__ __align__(16) bf16 g_wn2H[128 * 256],  g_wn2L[128 * 256];
__device__ __align__(16) bf16 g_wrH[256 * 128],   g_wrL[256 * 128];
__device__ float g_bg[1024];         // permuted combined gate bias
// misc
__device__ float g_deg[NN];
__device__ int g_cnt[NN];
__device__ int g_csr[NN];
__device__ int g_cur[NN];
__device__ int g_srcv[EE];           // src node per CSR slot (direct, no eid hop)
__device__ int g_bsum[256];

// ---------------------------- helpers -----------------------------------------
__device__ __forceinline__ uint32_t sm2u(const void* p) {
    return (uint32_t)__cvta_generic_to_shared(p);
}
__device__ __forceinline__ uint32_t pk(bf16 a, bf16 b) {
    return (uint32_t)__bfloat16_as_ushort(a) |
           ((uint32_t)__bfloat16_as_ushort(b) << 16);
}
__device__ __forceinline__ void split2(float a, float b, uint32_t& hi, uint32_t& lo) {
    const bf16 ha = __float2bfloat16_rn(a), hb = __float2bfloat16_rn(b);
    hi = pk(ha, hb);
    lo = pk(__float2bfloat16_rn(a - __bfloat162float(ha)),
            __float2bfloat16_rn(b - __bfloat162float(hb)));
}
__device__ __forceinline__ void mma16(float* d, const uint32_t* a, const uint32_t* b) {
    asm volatile(
        "mma.sync.aligned.m16n8k16.row.col.f32.bf16.bf16.f32 "
        "{%0,%1,%2,%3}, {%4,%5,%6,%7}, {%8,%9}, {%0,%1,%2,%3};"
        : "+f"(d[0]), "+f"(d[1]), "+f"(d[2]), "+f"(d[3])
        : "r"(a[0]), "r"(a[1]), "r"(a[2]), "r"(a[3]), "r"(b[0]), "r"(b[1]));
}
__device__ __forceinline__ void ldsm4(uint32_t* r, uint32_t addr) {
    asm volatile(
        "ldmatrix.sync.aligned.m8n8.x4.shared.b16 {%0,%1,%2,%3}, [%4];"
        : "=r"(r[0]), "=r"(r[1]), "=r"(r[2]), "=r"(r[3]) : "r"(addr));
}
__device__ __forceinline__ void cpa16(uint32_t s, const void* g) {
    asm volatile("cp.async.cg.shared.global [%0], [%1], 16;" :: "r"(s), "l"(g));
}
__device__ __forceinline__ void cpcommit() {
    asm volatile("cp.async.commit_group;" ::: "memory");
}
template <int N>
__device__ __forceinline__ void cpwait() {
    asm volatile("cp.async.wait_group %0;" :: "n"(N) : "memory");
}
__device__ __forceinline__ float sigm(float x) {
    return __fdividef(1.f, 1.f + __expf(-x));
}
__device__ __forceinline__ float ftanh(float x) {
    const float e = __expf(2.f * x);
    return __fdividef(e - 1.f, e + 1.f);
}

// =============================================================================
// Shared GEMM core pieces (BM=128, BN=128, BK=32; 256 thr = 8 warps 4m x 2n)
// =============================================================================
#define AP 40
#define STG_ELT 20480              // bf16 elements per stage (40960 B)
#define TG_SMEM (2 * STG_ELT * 2)  // bytes

__device__ __forceinline__ void tg_issue(
    const bf16* pAh, const bf16* pAl, int ldA, int rowBase,
    const bf16* pWh, const bf16* pWl, int ldW, int colBase,
    int kk0, bf16* sb, int tid)
{
#pragma unroll
    for (int i = 0; i < 2; i++) {
        const int idx = tid + 256 * i;
        const int r = idx >> 2, c8 = (idx & 3) * 8;
        const int so = r * AP + c8;
        cpa16(sm2u(sb + so),        pAh + (size_t)(rowBase + r) * ldA + kk0 + c8);
        cpa16(sm2u(sb + 5120 + so), pAl + (size_t)(rowBase + r) * ldA + kk0 + c8);
        cpa16(sm2u(sb + 10240 + so), pWh + (size_t)(colBase + r) * ldW + kk0 + c8);
        cpa16(sm2u(sb + 15360 + so), pWl + (size_t)(colBase + r) * ldW + kk0 + c8);
    }
    cpcommit();
}

// mainloop producing acc[2][4][2][4] (bf16x3)
#define TG_MAINLOOP(ACC, DUAL_)                                                   \
    const int ncp = K >> 5, total = (DUAL_) ? 2 * ncp : ncp;                      \
    tg_issue(Ah_, Al_, ldA, rowBase, Wh_, Wl_, ldW, colBase, 0, sm, tid);         \
    _Pragma("unroll 1")                                                           \
    for (int c = 0; c < total; c++) {                                             \
        if (c + 1 < total) {                                                      \
            const int n = c + 1;                                                  \
            const int ph = (DUAL_) ? (n >= ncp) : 0;                              \
            tg_issue(ph ? A2h : Ah_, ph ? A2l : Al_, ldA, rowBase,                \
                     ph ? W2h : Wh_, ph ? W2l : Wl_, ldW, colBase,                \
                     (ph ? n - ncp : n) << 5, sm + (n & 1) * STG_ELT, tid);       \
            cpwait<1>();                                                          \
        } else {                                                                  \
            cpwait<0>();                                                          \
        }                                                                         \
        __syncthreads();                                                          \
        const uint32_t base = sm2u(sm) + (uint32_t)(c & 1) * (STG_ELT * 2);       \
        _Pragma("unroll")                                                         \
        for (int kk = 0; kk < 32; kk += 16) {                                     \
            uint32_t ah[2][4], al[2][4], bh[4][4], bl[4][4];                      \
            _Pragma("unroll")                                                     \
            for (int mt = 0; mt < 2; mt++) {                                      \
                const uint32_t off =                                              \
                    (uint32_t)((wy * 32 + mt * 16 + (lane & 15)) * AP +           \
                               kk + ((lane >> 4) << 3)) * 2;                      \
                ldsm4(ah[mt], base + off);                                        \
                ldsm4(al[mt], base + 10240 + off);                                \
            }                                                                     \
            _Pragma("unroll")                                                     \
            for (int nb = 0; nb < 4; nb++) {                                      \
                const uint32_t off =                                              \
                    (uint32_t)((wx * 64 + nb * 16 + (lane & 7) +                  \
                                (((lane >> 4) & 1) << 3)) * AP +                  \
                               kk + (((lane >> 3) & 1) << 3)) * 2;                \
                ldsm4(bh[nb], base + 20480 + off);                                \
                ldsm4(bl[nb], base + 30720 + off);                                \
            }                                                                     \
            _Pragma("unroll")                                                     \
            for (int mt = 0; mt < 2; mt++)                                        \
                _Pragma("unroll")                                                 \
                for (int nb = 0; nb < 4; nb++)                                    \
                    _Pragma("unroll")                                             \
                    for (int h = 0; h < 2; h++) {                                 \
                        mma16(ACC[mt][nb][h], ah[mt], &bh[nb][2 * h]);            \
                        mma16(ACC[mt][nb][h], ah[mt], &bl[nb][2 * h]);            \
                        mma16(ACC[mt][nb][h], al[mt], &bh[nb][2 * h]);            \
                    }                                                             \
        }                                                                         \
        __syncthreads();                                                          \
    }

// =============================================================================
// Generic GEMM: C = act(A@W^T [+ A2@W2^T] + bias [+bias2]) -> hi/lo planes
// =============================================================================
template <int RELU_OUT, int DEGBIAS, int DUAL>
__global__ __launch_bounds__(256) void tg(
    const bf16* __restrict__ Ah_, const bf16* __restrict__ Al_,
    const bf16* __restrict__ A2h, const bf16* __restrict__ A2l, int ldA,
    const bf16* __restrict__ Wh_, const bf16* __restrict__ Wl_,
    const bf16* __restrict__ W2h, const bf16* __restrict__ W2l, int ldW, int K,
    const float* __restrict__ bias, const float* __restrict__ bias2,
    const float* __restrict__ deg,
    bf16* __restrict__ Ch, bf16* __restrict__ Cl, int ldC)
{
    extern __shared__ bf16 sm[];
    const int tid = threadIdx.x, warp = tid >> 5, lane = tid & 31;
    const int wy = warp >> 1, wx = warp & 1;
    const int g = lane >> 2, tg2 = lane & 3;
    const int rowBase = blockIdx.y * 128, colBase = blockIdx.x * 128;

    float acc[2][4][2][4];
#pragma unroll
    for (int a = 0; a < 2; a++)
#pragma unroll
        for (int b = 0; b < 4; b++)
#pragma unroll
            for (int c = 0; c < 2; c++)
#pragma unroll
                for (int d = 0; d < 4; d++) acc[a][b][c][d] = 0.f;

    TG_MAINLOOP(acc, DUAL)

#pragma unroll
    for (int mt = 0; mt < 2; mt++) {
        const int row = rowBase + wy * 32 + mt * 16 + g;
        const float d0 = DEGBIAS ? deg[row] : 1.f;
        const float d1 = DEGBIAS ? deg[row + 8] : 1.f;
#pragma unroll
        for (int nb = 0; nb < 4; nb++)
#pragma unroll
            for (int h = 0; h < 2; h++) {
                const int col = colBase + wx * 64 + nb * 16 + h * 8 + 2 * tg2;
                float bb0 = 0.f, bb1 = 0.f;
                if (bias)  { bb0 = bias[col];  bb1 = bias[col + 1]; }
                if (DUAL && bias2) { bb0 += bias2[col]; bb1 += bias2[col + 1]; }
                float v0 = acc[mt][nb][h][0] + d0 * bb0;
                float v1 = acc[mt][nb][h][1] + d0 * bb1;
                float v2 = acc[mt][nb][h][2] + d1 * bb0;
                float v3 = acc[mt][nb][h][3] + d1 * bb1;
                if (RELU_OUT) {
                    v0 = fmaxf(v0, 0.f); v1 = fmaxf(v1, 0.f);
                    v2 = fmaxf(v2, 0.f); v3 = fmaxf(v3, 0.f);
                }
                uint32_t hi, lo;
                split2(v0, v1, hi, lo);
                *(uint32_t*)&Ch[(size_t)row * ldC + col] = hi;
                *(uint32_t*)&Cl[(size_t)row * ldC + col] = lo;
                split2(v2, v3, hi, lo);
                *(uint32_t*)&Ch[(size_t)(row + 8) * ldC + col] = hi;
                *(uint32_t*)&Cl[(size_t)(row + 8) * ldC + col] = lo;
            }
    }
}

// =============================================================================
// Fused gates GEMM + LSTM. Weights gate-interleaved (col = 4*unit + gate,
// gate order i,f,g,o). Block tile = 128 rows x 32 LSTM units. Epilogue stages
// fp32 gates in smem, applies LSTM pointwise, writes h1/c1 (fp32) +
// relu(h1) hi/lo planes, all coalesced.
// =============================================================================
#define EPI_PITCH 132

__global__ __launch_bounds__(256) void tglstm(
    const bf16* __restrict__ Ah_, const bf16* __restrict__ Al_,
    const bf16* __restrict__ A2h, const bf16* __restrict__ A2l, int ldA,
    const bf16* __restrict__ Wh_, const bf16* __restrict__ Wl_,
    const bf16* __restrict__ W2h, const bf16* __restrict__ W2l, int ldW, int K,
    const float* __restrict__ bgate,   // permuted b_ih+b_hh [1024]
    const float* __restrict__ c0,
    float* __restrict__ h1, float* __restrict__ c1,
    bf16* __restrict__ rhh, bf16* __restrict__ rhl)
{
    extern __shared__ bf16 sm[];
    const int tid = threadIdx.x, warp = tid >> 5, lane = tid & 31;
    const int wy = warp >> 1, wx = warp & 1;
    const int g = lane >> 2, tg2 = lane & 3;
    const int rowBase = blockIdx.y * 128, colBase = blockIdx.x * 128;

    float acc[2][4][2][4];
#pragma unroll
    for (int a = 0; a < 2; a++)
#pragma unroll
        for (int b = 0; b < 4; b++)
#pragma unroll
            for (int c = 0; c < 2; c++)
#pragma unroll
                for (int d = 0; d < 4; d++) acc[a][b][c][d] = 0.f;

    TG_MAINLOOP(acc, 1)

    // ---- stage gates (with bias) into smem fp32 [128][EPI_PITCH] ----
    float* st = (float*)sm;
#pragma unroll
    for (int mt = 0; mt < 2; mt++) {
        const int row = wy * 32 + mt * 16 + g;
#pragma unroll
        for (int nb = 0; nb < 4; nb++)
#pragma unroll
            for (int h = 0; h < 2; h++) {
                const int col = wx * 64 + nb * 16 + h * 8 + 2 * tg2;
                const float b0 = bgate[colBase + col];
                const float b1 = bgate[colBase + col + 1];
                st[row * EPI_PITCH + col]           = acc[mt][nb][h][0] + b0;
                st[row * EPI_PITCH + col + 1]       = acc[mt][nb][h][1] + b1;
                st[(row + 8) * EPI_PITCH + col]     = acc[mt][nb][h][2] + b0;
                st[(row + 8) * EPI_PITCH + col + 1] = acc[mt][nb][h][3] + b1;
            }
    }
    __syncthreads();

    // ---- LSTM pointwise: 128 rows x 32 units ----
    const int uBase = colBase >> 2;                  // 32 units per tile
#pragma unroll
    for (int i = 0; i < 16; i++) {
        const int idx = tid + 256 * i;               // 4096 = 128 x 32
        const int r = idx >> 5, u = idx & 31;
        const float* gp = st + r * EPI_PITCH + u * 4;
        const float ig = sigm(gp[0]);
        const float fg = sigm(gp[1]);
        const float gg = ftanh(gp[2]);
        const float og = sigm(gp[3]);
        const size_t o = (size_t)(rowBase + r) * 256 + uBase + u;
        const float cv = fg * c0[o] + ig * gg;
        const float hv = og * ftanh(cv);
        c1[o] = cv;
        h1[o] = hv;
        const float rv = fmaxf(hv, 0.f);
        const bf16 hb = __float2bfloat16_rn(rv);
        rhh[o] = hb;
        rhl[o] = __float2bfloat16_rn(rv - __bfloat162float(hb));
    }
}

// =============================================================================
// fp32 -> bf16 hi/lo plane split
// =============================================================================
__global__ __launch_bounds__(256) void split_kernel(
    const float4* __restrict__ in, uint2* __restrict__ hi, uint2* __restrict__ lo)
{
    const int idx = blockIdx.x * 256 + threadIdx.x;
    const float4 v = in[idx];
    uint32_t h0, l0, h1, l1;
    split2(v.x, v.y, h0, l0);
    split2(v.z, v.w, h1, l1);
    hi[idx] = make_uint2(h0, h1);
    lo[idx] = make_uint2(l0, l1);
}

// split with gate-interleave row permutation: out row' = unit*4+gate for
// in row = gate*256+unit. ldW = 256 (w_ih/w_hh). grid = 1024*256/1024.
__global__ __launch_bounds__(256) void split_perm_kernel(
    const float4* __restrict__ in, uint2* __restrict__ hi, uint2* __restrict__ lo)
{
    const int idx = blockIdx.x * 256 + threadIdx.x;   // float4 index
    const int r = idx >> 6, c = idx & 63;             // row, float4-col (256/4)
    const int gate = r >> 8, unit = r & 255;
    const int rp = unit * 4 + gate;
    const float4 v = in[idx];
    uint32_t h0, l0, h1, l1;
    split2(v.x, v.y, h0, l0);
    split2(v.z, v.w, h1, l1);
    hi[rp * 64 + c] = make_uint2(h0, h1);
    lo[rp * 64 + c] = make_uint2(l0, l1);
}

__global__ __launch_bounds__(256) void bias_perm_kernel(
    const float* __restrict__ b_ih, const float* __restrict__ b_hh,
    float* __restrict__ bg)
{
    const int r = blockIdx.x * 256 + threadIdx.x;     // 1024
    const int gate = r >> 8, unit = r & 255;
    bg[unit * 4 + gate] = b_ih[r] + b_hh[r];
}

// =============================================================================
// CSR build
// =============================================================================
__global__ __launch_bounds__(256) void zero_int_kernel(int* __restrict__ p)
{
    p[blockIdx.x * 256 + threadIdx.x] = 0;
}
__global__ __launch_bounds__(256) void hist_kernel(const int* __restrict__ dst,
                                                   int* __restrict__ cnt)
{
    atomicAdd(&cnt[dst[blockIdx.x * 256 + threadIdx.x]], 1);
}
__global__ __launch_bounds__(256) void scan1_kernel(
    const int* __restrict__ cnt, int* __restrict__ csr, int* __restrict__ bsum)
{
    __shared__ int s[256];
    const int t = threadIdx.x, b = blockIdx.x;
    const int v = cnt[b * 256 + t];
    s[t] = v; __syncthreads();
#pragma unroll
    for (int off = 1; off < 256; off <<= 1) {
        int x = (t >= off) ? s[t - off] : 0;
        __syncthreads();
        s[t] += x;
        __syncthreads();
    }
    csr[b * 256 + t] = s[t] - v;
    if (t == 255) bsum[b] = s[255];
}
__global__ __launch_bounds__(256) void scan2_kernel(int* __restrict__ bsum)
{
    __shared__ int s[256];
    const int t = threadIdx.x;
    const int v = bsum[t];
    s[t] = v; __syncthreads();
#pragma unroll
    for (int off = 1; off < 256; off <<= 1) {
        int x = (t >= off) ? s[t - off] : 0;
        __syncthreads();
        s[t] += x;
        __syncthreads();
    }
    bsum[t] = s[t] - v;
}
__global__ __launch_bounds__(256) void scan3_kernel(
    int* __restrict__ csr, const int* __restrict__ bsum, int* __restrict__ cur)
{
    const int i = blockIdx.x * 256 + threadIdx.x;
    const int x = csr[i] + bsum[i >> 8];
    csr[i] = x;
    cur[i] = x;
}
__global__ __launch_bounds__(256) void scatter_src_kernel(
    const int* __restrict__ dst, const int* __restrict__ src,
    int* __restrict__ cur, int* __restrict__ srcv)
{
    const int e = blockIdx.x * 256 + threadIdx.x;
    const int p = atomicAdd(&cur[dst[e]], 1);
    srcv[p] = src[e];
}

// =============================================================================
// Edge gather: warp per node d: aggH[d] = sum relu(U[srcv]+V[d]); deg=cnt
// =============================================================================
__device__ __forceinline__ void unpack8(uint4 h, uint4 l, float* o) {
    const __nv_bfloat162* hp = (const __nv_bfloat162*)&h;
    const __nv_bfloat162* lp = (const __nv_bfloat162*)&l;
#pragma unroll
    for (int j = 0; j < 4; j++) {
        const float2 fh = __bfloat1622float2(hp[j]);
        const float2 fl = __bfloat1622float2(lp[j]);
        o[2 * j] = fh.x + fl.x;
        o[2 * j + 1] = fh.y + fl.y;
    }
}

__global__ __launch_bounds__(256) void gather_kernel(
    const bf16* __restrict__ Uh, const bf16* __restrict__ Ul,
    const bf16* __restrict__ Vh, const bf16* __restrict__ Vl,
    const int* __restrict__ srcv,
    const int* __restrict__ csr, const int* __restrict__ cnt,
    bf16* __restrict__ aggHh, bf16* __restrict__ aggHl, float* __restrict__ deg)
{
    const int d = blockIdx.x * 8 + (threadIdx.x >> 5);
    const int l = threadIdx.x & 31;
    const int start = csr[d];
    const int n = cnt[d];

    float v[8];
    unpack8(((const uint4*)(Vh + (size_t)d * 256))[l],
            ((const uint4*)(Vl + (size_t)d * 256))[l], v);
    float a[8];
#pragma unroll
    for (int j = 0; j < 8; j++) a[j] = 0.f;

    const int nw = n < 32 ? n : 32;
    int myS = 0;
    if (l < nw) myS = srcv[start + l];
    for (int i = 0; i < nw; i++) {
        const int s = __shfl_sync(0xffffffffu, myS, i);
        float u[8];
        unpack8(((const uint4*)(Uh + (size_t)s * 256))[l],
                ((const uint4*)(Ul + (size_t)s * 256))[l], u);
#pragma unroll
        for (int j = 0; j < 8; j++) a[j] += fmaxf(u[j] + v[j], 0.f);
    }
    for (int i = 32; i < n; i++) {
        const int s = srcv[start + i];
        float u[8];
        unpack8(((const uint4*)(Uh + (size_t)s * 256))[l],
                ((const uint4*)(Ul + (size_t)s * 256))[l], u);
#pragma unroll
        for (int j = 0; j < 8; j++) a[j] += fmaxf(u[j] + v[j], 0.f);
    }

    uint4 oh, ol;
    split2(a[0], a[1], oh.x, ol.x);
    split2(a[2], a[3], oh.y, ol.y);
    split2(a[4], a[5], oh.z, ol.z);
    split2(a[6], a[7], oh.w, ol.w);
    ((uint4*)(aggHh + (size_t)d * 256))[l] = oh;
    ((uint4*)(aggHl + (size_t)d * 256))[l] = ol;
    if (l == 0) deg[d] = (float)n;
}

// =============================================================================
// Readout second layer
// =============================================================================
__global__ __launch_bounds__(256) void logits_kernel(
    const bf16* __restrict__ r1h, const bf16* __restrict__ r1l,
    const float* __restrict__ wr2, const float* __restrict__ br2,
    float* __restrict__ out)
{
    __shared__ float sw[8 * 257];
    const int tid = threadIdx.x;
    for (int i = tid; i < 2048; i += 256)
        sw[(i >> 8) * 257 + (i & 255)] = wr2[i];
    __syncthreads();

    const int row = blockIdx.x * 32 + (tid >> 3);
    const int o = tid & 7;
    const __nv_bfloat162* ah = (const __nv_bfloat162*)(r1h + (size_t)row * 256);
    const __nv_bfloat162* al = (const __nv_bfloat162*)(r1l + (size_t)row * 256);
    const float* w = sw + o * 257;
    float acc = 0.f;
#pragma unroll 8
    for (int k = 0; k < 128; k++) {
        const float2 h = __bfloat1622float2(ah[k]);
        const float2 l = __bfloat1622float2(al[k]);
        acc = fmaf(h.x + l.x, w[2 * k], acc);
        acc = fmaf(h.y + l.y, w[2 * k + 1], acc);
    }
    out[(size_t)row * 8 + o] = acc + br2[o];
}

// =============================================================================
// Launcher
// =============================================================================
#define GSYM(var, sym) cudaGetSymbolAddress((void**)&var, sym)

extern "C" void kernel_launch(void* const* d_in, const int* in_sizes, int n_in,
                              void* d_out, int out_size)
{
    const float* obs  = (const float*)d_in[0];
    const float* h0   = (const float*)d_in[1];
    const float* c0   = (const float*)d_in[2];
    const int*   src  = (const int*)d_in[3];
    const int*   dst  = (const int*)d_in[4];
    const float* w1a  = (const float*)d_in[5];
    const float* b1a  = (const float*)d_in[6];
    const float* w1b  = (const float*)d_in[7];
    const float* b1b  = (const float*)d_in[8];
    const float* w_ih = (const float*)d_in[9];
    const float* b_ih = (const float*)d_in[10];
    const float* w_hh = (const float*)d_in[11];
    const float* b_hh = (const float*)d_in[12];
    const float* w1   = (const float*)d_in[13];
    const float* b1   = (const float*)d_in[14];
    const float* we   = (const float*)d_in[15];
    const float* be   = (const float*)d_in[16];
    const float* we2  = (const float*)d_in[17];
    const float* be2  = (const float*)d_in[18];
    const float* wn   = (const float*)d_in[19];
    const float* bn   = (const float*)d_in[20];
    const float* wn2  = (const float*)d_in[21];
    const float* bn2  = (const float*)d_in[22];
    const float* wr   = (const float*)d_in[23];
    const float* br   = (const float*)d_in[24];
    const float* wr2  = (const float*)d_in[25];
    const float* br2  = (const float*)d_in[26];

    float* out    = (float*)d_out;
    float* logits = out;                       // [N, 8]
    float* h1     = out + (size_t)NN * 8;      // [N, 256]
    float* c1     = h1 + (size_t)NN * 256;     // [N, 256]

    bf16 *obsH, *obsL, *h0H, *h0L, *t1H, *t1L, *xH, *xL, *rhH, *rhL,
         *nfH, *nfL, *UH, *UL, *VH, *VL, *aHH, *aHL, *aEH, *aEL, *nhH, *nhL,
         *n2H, *n2L, *r1H, *r1L;
    bf16 *w1aH, *w1aL, *w1bH, *w1bL, *wihH, *wihL, *whhH, *whhL, *w1H, *w1L,
         *weH, *weL, *we2H, *we2L, *wnH, *wnL, *wn2H, *wn2L, *wrH, *wrL;
    float *p_deg, *p_bg;
    int *p_cnt, *p_csr, *p_cur, *p_srcv, *p_bsum;

    GSYM(obsH, g_obsH); GSYM(obsL, g_obsL); GSYM(h0H, g_h0H); GSYM(h0L, g_h0L);
    GSYM(t1H, g_t1H);   GSYM(t1L, g_t1L);   GSYM(xH, g_xH);   GSYM(xL, g_xL);
    GSYM(rhH, g_rhH);   GSYM(rhL, g_rhL);
    GSYM(nfH, g_nfH);   GSYM(nfL, g_nfL);   GSYM(UH, g_UH);   GSYM(UL, g_UL);
    GSYM(VH, g_VH);     GSYM(VL, g_VL);     GSYM(aHH, g_aHH); GSYM(aHL, g_aHL);
    GSYM(aEH, g_aEH);   GSYM(aEL, g_aEL);   GSYM(nhH, g_nhH); GSYM(nhL, g_nhL);
    GSYM(n2H, g_n2H);   GSYM(n2L, g_n2L);   GSYM(r1H, g_r1H); GSYM(r1L, g_r1L);
    GSYM(w1aH, g_w1aH); GSYM(w1aL, g_w1aL); GSYM(w1bH, g_w1bH); GSYM(w1bL, g_w1bL);
    GSYM(wihH, g_wihH); GSYM(wihL, g_wihL); GSYM(whhH, g_whhH); GSYM(whhL, g_whhL);
    GSYM(w1H, g_w1H);   GSYM(w1L, g_w1L);   GSYM(weH, g_weH);   GSYM(weL, g_weL);
    GSYM(we2H, g_we2H); GSYM(we2L, g_we2L); GSYM(wnH, g_wnH);   GSYM(wnL, g_wnL);
    GSYM(wn2H, g_wn2H); GSYM(wn2L, g_wn2L); GSYM(wrH, g_wrH);   GSYM(wrL, g_wrL);
    GSYM(p_bg, g_bg);   GSYM(p_deg, g_deg);
    GSYM(p_cnt, g_cnt); GSYM(p_csr, g_csr); GSYM(p_cur, g_cur);
    GSYM(p_srcv, g_srcv); GSYM(p_bsum, g_bsum);

    cudaFuncSetAttribute(tg<1,0,0>, cudaFuncAttributeMaxDynamicSharedMemorySize, TG_SMEM);
    cudaFuncSetAttribute(tg<0,0,0>, cudaFuncAttributeMaxDynamicSharedMemorySize, TG_SMEM);
    cudaFuncSetAttribute(tg<0,1,0>, cudaFuncAttributeMaxDynamicSharedMemorySize, TG_SMEM);
    cudaFuncSetAttribute(tg<1,0,1>, cudaFuncAttributeMaxDynamicSharedMemorySize, TG_SMEM);
    cudaFuncSetAttribute(tglstm, cudaFuncAttributeMaxDynamicSharedMemorySize, TG_SMEM);

    const dim3 blk(256);
    const int MT = NN / 128;   // 512 row tiles

    // ---- plane splits ----
    split_kernel<<<NN * 256 / 1024, blk>>>((const float4*)obs, (uint2*)obsH, (uint2*)obsL);
    split_kernel<<<NN * 256 / 1024, blk>>>((const float4*)h0, (uint2*)h0H, (uint2*)h0L);
    split_kernel<<<512 * 256 / 1024, blk>>>((const float4*)w1a, (uint2*)w1aH, (uint2*)w1aL);
    split_kernel<<<256 * 512 / 1024, blk>>>((const float4*)w1b, (uint2*)w1bH, (uint2*)w1bL);
    split_perm_kernel<<<1024 * 256 / 1024, blk>>>((const float4*)w_ih, (uint2*)wihH, (uint2*)wihL);
    split_perm_kernel<<<1024 * 256 / 1024, blk>>>((const float4*)w_hh, (uint2*)whhH, (uint2*)whhL);
    bias_perm_kernel<<<4, blk>>>(b_ih, b_hh, p_bg);
    split_kernel<<<128 * 256 / 1024, blk>>>((const float4*)w1, (uint2*)w1H, (uint2*)w1L);
    split_kernel<<<256 * 256 / 1024, blk>>>((const float4*)we, (uint2*)weH, (uint2*)weL);
    split_kernel<<<128 * 256 / 1024, blk>>>((const float4*)we2, (uint2*)we2H, (uint2*)we2L);
    split_kernel<<<256 * 256 / 1024, blk>>>((const float4*)wn, (uint2*)wnH, (uint2*)wnL);
    split_kernel<<<128 * 256 / 1024, blk>>>((const float4*)wn2, (uint2*)wn2H, (uint2*)wn2L);
    split_kernel<<<256 * 128 / 1024, blk>>>((const float4*)wr, (uint2*)wrH, (uint2*)wrL);

    // ---- CSR build ----
    zero_int_kernel<<<NN / 256, blk>>>(p_cnt);
    hist_kernel<<<EE / 256, blk>>>(dst, p_cnt);
    scan1_kernel<<<256, blk>>>(p_cnt, p_csr, p_bsum);
    scan2_kernel<<<1, blk>>>(p_bsum);
    scan3_kernel<<<256, blk>>>(p_csr, p_bsum, p_cur);
    scatter_src_kernel<<<EE / 256, blk>>>(dst, src, p_cur, p_srcv);

    // 1. t1 = relu(obs @ w1a^T + b1a)                        [N,512] K=256
    tg<1,0,0><<<dim3(4, MT), blk, TG_SMEM>>>(obsH, obsL, nullptr, nullptr, 256,
                                             w1aH, w1aL, nullptr, nullptr, 256, 256,
                                             b1a, nullptr, nullptr, t1H, t1L, 512);
    // 2. x = t1 @ w1b^T + b1b                                [N,256] K=512
    tg<0,0,0><<<dim3(2, MT), blk, TG_SMEM>>>(t1H, t1L, nullptr, nullptr, 512,
                                             w1bH, w1bL, nullptr, nullptr, 512, 512,
                                             b1b, nullptr, nullptr, xH, xL, 256);
    // 3+4. fused gates GEMM + LSTM -> h1, c1, relu(h1) planes
    tglstm<<<dim3(8, MT), blk, TG_SMEM>>>(xH, xL, h0H, h0L, 256,
                                          wihH, wihL, whhH, whhL, 256, 256,
                                          p_bg, c0, h1, c1, rhH, rhL);
    // 5. nf = relu(h1) @ w1^T + b1                           [N,128] K=256
    tg<0,0,0><<<dim3(1, MT), blk, TG_SMEM>>>(rhH, rhL, nullptr, nullptr, 256,
                                             w1H, w1L, nullptr, nullptr, 256, 256,
                                             b1, nullptr, nullptr, nfH, nfL, 128);
    // 6a. U = nf @ weL^T + be                                [N,256] K=128
    tg<0,0,0><<<dim3(2, MT), blk, TG_SMEM>>>(nfH, nfL, nullptr, nullptr, 128,
                                             weH, weL, nullptr, nullptr, 256, 128,
                                             be, nullptr, nullptr, UH, UL, 256);
    // 6b. V = nf @ weR^T                                     [N,256] K=128
    tg<0,0,0><<<dim3(2, MT), blk, TG_SMEM>>>(nfH, nfL, nullptr, nullptr, 128,
                                             weH + 128, weL + 128, nullptr, nullptr, 256, 128,
                                             nullptr, nullptr, nullptr, VH, VL, 256);
    // 7. gather: aggH[d] = sum relu(U[src]+V[d]); deg[d]=cnt[d]
    gather_kernel<<<NN / 8, blk>>>(UH, UL, VH, VL, p_srcv, p_csr, p_cnt,
                                   aHH, aHL, p_deg);
    // 8. aggE = aggH @ we2^T + deg*be2                       [N,128] K=256
    tg<0,1,0><<<dim3(1, MT), blk, TG_SMEM>>>(aHH, aHL, nullptr, nullptr, 256,
                                             we2H, we2L, nullptr, nullptr, 256, 256,
                                             be2, nullptr, p_deg, aEH, aEL, 128);
    // 9. nh = relu(nf@wnL^T + aggE@wnR^T + bn)               [N,256]
    tg<1,0,1><<<dim3(2, MT), blk, TG_SMEM>>>(nfH, nfL, aEH, aEL, 128,
                                             wnH, wnL, wnH + 128, wnL + 128, 256, 128,
                                             bn, nullptr, nullptr, nhH, nhL, 256);
    // 10. nf2 = nh @ wn2^T + bn2                             [N,128] K=256
    tg<0,0,0><<<dim3(1, MT), blk, TG_SMEM>>>(nhH, nhL, nullptr, nullptr, 256,
                                             wn2H, wn2L, nullptr, nullptr, 256, 256,
                                             bn2, nullptr, nullptr, n2H, n2L, 128);
    // 11. r1 = relu(nf2 @ wr^T + br)                         [N,256] K=128
    tg<1,0,0><<<dim3(2, MT), blk, TG_SMEM>>>(n2H, n2L, nullptr, nullptr, 128,
                                             wrH, wrL, nullptr, nullptr, 128, 128,
                                             br, nullptr, nullptr, r1H, r1L, 256);
    // 12. logits = r1 @ wr2^T + br2                          [N,8]
    logits_kernel<<<NN / 32, blk>>>(r1H, r1L, wr2, br2, logits);
}

// round 11
// speedup vs baseline: 5.9553x; 1.0130x over previous
#include <cuda_runtime.h>
#include <cuda_bf16.h>
#include <math.h>
#include <stdint.h>

#define NN 65536
#define EE 524288
// dims: OBS=256 HID=512 MID=256 LSTM=256 DOUT=128 DLAST=128 RFM=256 LH=256 ACT=8

typedef __nv_bfloat16 bf16;

// ---------------- scratch (device globals; no allocation allowed) -------------
__device__ __align__(16) bf16 g_obsH[NN * 256], g_obsL[NN * 256];
__device__ __align__(16) bf16 g_h0H[NN * 256],  g_h0L[NN * 256];
__device__ __align__(16) bf16 g_t1H[NN * 512],  g_t1L[NN * 512];
__device__ __align__(16) bf16 g_xH[NN * 256],   g_xL[NN * 256];
__device__ __align__(16) bf16 g_rhH[NN * 256],  g_rhL[NN * 256];
__device__ __align__(16) bf16 g_nfH[NN * 128],  g_nfL[NN * 128];
__device__ __align__(16) bf16 g_UVH[NN * 512],  g_UVL[NN * 512];   // [U | V]
__device__ __align__(16) bf16 g_aHH[NN * 256],  g_aHL[NN * 256];
__device__ __align__(16) bf16 g_aEH[NN * 128],  g_aEL[NN * 128];
__device__ __align__(16) bf16 g_nhH[NN * 256],  g_nhL[NN * 256];
__device__ __align__(16) bf16 g_n2H[NN * 128],  g_n2L[NN * 128];
__device__ __align__(16) bf16 g_r1H[NN * 256],  g_r1L[NN * 256];
// weight planes (wih/whh gate-interleaved row' = unit*4+gate; wuv = [weL;weR])
__device__ __align__(16) bf16 g_w1aH[512 * 256],  g_w1aL[512 * 256];
__device__ __align__(16) bf16 g_w1bH[256 * 512],  g_w1bL[256 * 512];
__device__ __align__(16) bf16 g_wihH[1024 * 256], g_wihL[1024 * 256];
__device__ __align__(16) bf16 g_whhH[1024 * 256], g_whhL[1024 * 256];
__device__ __align__(16) bf16 g_w1H[128 * 256],   g_w1L[128 * 256];
__device__ __align__(16) bf16 g_wuvH[512 * 128],  g_wuvL[512 * 128];
__device__ __align__(16) bf16 g_we2H[128 * 256],  g_we2L[128 * 256];
__device__ __align__(16) bf16 g_wnH[256 * 256],   g_wnL[256 * 256];
__device__ __align__(16) bf16 g_wn2H[128 * 256],  g_wn2L[128 * 256];
__device__ __align__(16) bf16 g_wrH[256 * 128],   g_wrL[256 * 128];
__device__ float g_bg[1024];         // permuted combined gate bias
__device__ float g_buv[512];         // [be | 0]
// misc
__device__ float g_deg[NN];
__device__ int g_cnt[NN];
__device__ int g_csr[NN];
__device__ int g_cur[NN];
__device__ int g_srcv[EE];
__device__ int g_bsum[256];

// ---------------------------- helpers -----------------------------------------
__device__ __forceinline__ uint32_t sm2u(const void* p) {
    return (uint32_t)__cvta_generic_to_shared(p);
}
__device__ __forceinline__ uint32_t pk(bf16 a, bf16 b) {
    return (uint32_t)__bfloat16_as_ushort(a) |
           ((uint32_t)__bfloat16_as_ushort(b) << 16);
}
__device__ __forceinline__ void split2(float a, float b, uint32_t& hi, uint32_t& lo) {
    const bf16 ha = __float2bfloat16_rn(a), hb = __float2bfloat16_rn(b);
    hi = pk(ha, hb);
    lo = pk(__float2bfloat16_rn(a - __bfloat162float(ha)),
            __float2bfloat16_rn(b - __bfloat162float(hb)));
}
__device__ __forceinline__ void mma16(float* d, const uint32_t* a, const uint32_t* b) {
    asm volatile(
        "mma.sync.aligned.m16n8k16.row.col.f32.bf16.bf16.f32 "
        "{%0,%1,%2,%3}, {%4,%5,%6,%7}, {%8,%9}, {%0,%1,%2,%3};"
        : "+f"(d[0]), "+f"(d[1]), "+f"(d[2]), "+f"(d[3])
        : "r"(a[0]), "r"(a[1]), "r"(a[2]), "r"(a[3]), "r"(b[0]), "r"(b[1]));
}
__device__ __forceinline__ void ldsm4(uint32_t* r, uint32_t addr) {
    asm volatile(
        "ldmatrix.sync.aligned.m8n8.x4.shared.b16 {%0,%1,%2,%3}, [%4];"
        : "=r"(r[0]), "=r"(r[1]), "=r"(r[2]), "=r"(r[3]) : "r"(addr));
}
__device__ __forceinline__ void cpa16(uint32_t s, const void* g) {
    asm volatile("cp.async.cg.shared.global [%0], [%1], 16;" :: "r"(s), "l"(g));
}
__device__ __forceinline__ void cpcommit() {
    asm volatile("cp.async.commit_group;" ::: "memory");
}
template <int N>
__device__ __forceinline__ void cpwait() {
    asm volatile("cp.async.wait_group %0;" :: "n"(N) : "memory");
}
__device__ __forceinline__ float sigm(float x) {
    return __fdividef(1.f, 1.f + __expf(-x));
}
__device__ __forceinline__ float ftanh(float x) {
    const float e = __expf(2.f * x);
    return __fdividef(e - 1.f, e + 1.f);
}

// =============================================================================
// Shared GEMM core (BM=128, BN=128, BK=32; 256 thr = 8 warps 4m x 2n)
// =============================================================================
#define AP 40
#define STG_ELT 20480              // bf16 elements per stage (40960 B)
#define TG_SMEM (2 * STG_ELT * 2)  // bytes

__device__ __forceinline__ void tg_issue(
    const bf16* pAh, const bf16* pAl, int ldA, int rowBase,
    const bf16* pWh, const bf16* pWl, int ldW, int colBase,
    int kk0, bf16* sb, int tid)
{
#pragma unroll
    for (int i = 0; i < 2; i++) {
        const int idx = tid + 256 * i;
        const int r = idx >> 2, c8 = (idx & 3) * 8;
        const int so = r * AP + c8;
        cpa16(sm2u(sb + so),        pAh + (size_t)(rowBase + r) * ldA + kk0 + c8);
        cpa16(sm2u(sb + 5120 + so), pAl + (size_t)(rowBase + r) * ldA + kk0 + c8);
        cpa16(sm2u(sb + 10240 + so), pWh + (size_t)(colBase + r) * ldW + kk0 + c8);
        cpa16(sm2u(sb + 15360 + so), pWl + (size_t)(colBase + r) * ldW + kk0 + c8);
    }
    cpcommit();
}

#define TG_MAINLOOP(ACC, DUAL_)                                                   \
    const int ncp = K >> 5, total = (DUAL_) ? 2 * ncp : ncp;                      \
    tg_issue(Ah_, Al_, ldA, rowBase, Wh_, Wl_, ldW, colBase, 0, sm, tid);         \
    _Pragma("unroll 1")                                                           \
    for (int c = 0; c < total; c++) {                                             \
        if (c + 1 < total) {                                                      \
            const int n = c + 1;                                                  \
            const int ph = (DUAL_) ? (n >= ncp) : 0;                              \
            tg_issue(ph ? A2h : Ah_, ph ? A2l : Al_, ldA, rowBase,                \
                     ph ? W2h : Wh_, ph ? W2l : Wl_, ldW, colBase,                \
                     (ph ? n - ncp : n) << 5, sm + (n & 1) * STG_ELT, tid);       \
            cpwait<1>();                                                          \
        } else {                                                                  \
            cpwait<0>();                                                          \
        }                                                                         \
        __syncthreads();                                                          \
        const uint32_t base = sm2u(sm) + (uint32_t)(c & 1) * (STG_ELT * 2);       \
        _Pragma("unroll")                                                         \
        for (int kk = 0; kk < 32; kk += 16) {                                     \
            uint32_t ah[2][4], al[2][4], bh[4][4], bl[4][4];                      \
            _Pragma("unroll")                                                     \
            for (int mt = 0; mt < 2; mt++) {                                      \
                const uint32_t off =                                              \
                    (uint32_t)((wy * 32 + mt * 16 + (lane & 15)) * AP +           \
                               kk + ((lane >> 4) << 3)) * 2;                      \
                ldsm4(ah[mt], base + off);                                        \
                ldsm4(al[mt], base + 10240 + off);                                \
            }                                                                     \
            _Pragma("unroll")                                                     \
            for (int nb = 0; nb < 4; nb++) {                                      \
                const uint32_t off =                                              \
                    (uint32_t)((wx * 64 + nb * 16 + (lane & 7) +                  \
                                (((lane >> 4) & 1) << 3)) * AP +                  \
                               kk + (((lane >> 3) & 1) << 3)) * 2;                \
                ldsm4(bh[nb], base + 20480 + off);                                \
                ldsm4(bl[nb], base + 30720 + off);                                \
            }                                                                     \
            _Pragma("unroll")                                                     \
            for (int mt = 0; mt < 2; mt++)                                        \
                _Pragma("unroll")                                                 \
                for (int nb = 0; nb < 4; nb++)                                    \
                    _Pragma("unroll")                                             \
                    for (int h = 0; h < 2; h++) {                                 \
                        mma16(ACC[mt][nb][h], ah[mt], &bh[nb][2 * h]);            \
                        mma16(ACC[mt][nb][h], ah[mt], &bl[nb][2 * h]);            \
                        mma16(ACC[mt][nb][h], al[mt], &bh[nb][2 * h]);            \
                    }                                                             \
        }                                                                         \
        __syncthreads();                                                          \
    }

// =============================================================================
// Generic GEMM: C = act(A@W^T [+ A2@W2^T] + bias [+bias2]) -> hi/lo planes
// =============================================================================
template <int RELU_OUT, int DEGBIAS, int DUAL>
__global__ __launch_bounds__(256) void tg(
    const bf16* __restrict__ Ah_, const bf16* __restrict__ Al_,
    const bf16* __restrict__ A2h, const bf16* __restrict__ A2l, int ldA,
    const bf16* __restrict__ Wh_, const bf16* __restrict__ Wl_,
    const bf16* __restrict__ W2h, const bf16* __restrict__ W2l, int ldW, int K,
    const float* __restrict__ bias, const float* __restrict__ bias2,
    const float* __restrict__ deg,
    bf16* __restrict__ Ch, bf16* __restrict__ Cl, int ldC)
{
    extern __shared__ bf16 sm[];
    const int tid = threadIdx.x, warp = tid >> 5, lane = tid & 31;
    const int wy = warp >> 1, wx = warp & 1;
    const int g = lane >> 2, tg2 = lane & 3;
    const int rowBase = blockIdx.y * 128, colBase = blockIdx.x * 128;

    float acc[2][4][2][4];
#pragma unroll
    for (int a = 0; a < 2; a++)
#pragma unroll
        for (int b = 0; b < 4; b++)
#pragma unroll
            for (int c = 0; c < 2; c++)
#pragma unroll
                for (int d = 0; d < 4; d++) acc[a][b][c][d] = 0.f;

    TG_MAINLOOP(acc, DUAL)

#pragma unroll
    for (int mt = 0; mt < 2; mt++) {
        const int row = rowBase + wy * 32 + mt * 16 + g;
        const float d0 = DEGBIAS ? deg[row] : 1.f;
        const float d1 = DEGBIAS ? deg[row + 8] : 1.f;
#pragma unroll
        for (int nb = 0; nb < 4; nb++)
#pragma unroll
            for (int h = 0; h < 2; h++) {
                const int col = colBase + wx * 64 + nb * 16 + h * 8 + 2 * tg2;
                float bb0 = 0.f, bb1 = 0.f;
                if (bias)  { bb0 = bias[col];  bb1 = bias[col + 1]; }
                if (DUAL && bias2) { bb0 += bias2[col]; bb1 += bias2[col + 1]; }
                float v0 = acc[mt][nb][h][0] + d0 * bb0;
                float v1 = acc[mt][nb][h][1] + d0 * bb1;
                float v2 = acc[mt][nb][h][2] + d1 * bb0;
                float v3 = acc[mt][nb][h][3] + d1 * bb1;
                if (RELU_OUT) {
                    v0 = fmaxf(v0, 0.f); v1 = fmaxf(v1, 0.f);
                    v2 = fmaxf(v2, 0.f); v3 = fmaxf(v3, 0.f);
                }
                uint32_t hi, lo;
                split2(v0, v1, hi, lo);
                *(uint32_t*)&Ch[(size_t)row * ldC + col] = hi;
                *(uint32_t*)&Cl[(size_t)row * ldC + col] = lo;
                split2(v2, v3, hi, lo);
                *(uint32_t*)&Ch[(size_t)(row + 8) * ldC + col] = hi;
                *(uint32_t*)&Cl[(size_t)(row + 8) * ldC + col] = lo;
            }
    }
}

// =============================================================================
// Fused gates GEMM + LSTM (weights gate-interleaved; tile = 128 rows x 32 units)
// =============================================================================
#define EPI_PITCH 132

__global__ __launch_bounds__(256) void tglstm(
    const bf16* __restrict__ Ah_, const bf16* __restrict__ Al_,
    const bf16* __restrict__ A2h, const bf16* __restrict__ A2l, int ldA,
    const bf16* __restrict__ Wh_, const bf16* __restrict__ Wl_,
    const bf16* __restrict__ W2h, const bf16* __restrict__ W2l, int ldW, int K,
    const float* __restrict__ bgate,
    const float* __restrict__ c0,
    float* __restrict__ h1, float* __restrict__ c1,
    bf16* __restrict__ rhh, bf16* __restrict__ rhl)
{
    extern __shared__ bf16 sm[];
    const int tid = threadIdx.x, warp = tid >> 5, lane = tid & 31;
    const int wy = warp >> 1, wx = warp & 1;
    const int g = lane >> 2, tg2 = lane & 3;
    const int rowBase = blockIdx.y * 128, colBase = blockIdx.x * 128;

    float acc[2][4][2][4];
#pragma unroll
    for (int a = 0; a < 2; a++)
#pragma unroll
        for (int b = 0; b < 4; b++)
#pragma unroll
            for (int c = 0; c < 2; c++)
#pragma unroll
                for (int d = 0; d < 4; d++) acc[a][b][c][d] = 0.f;

    TG_MAINLOOP(acc, 1)

    float* st = (float*)sm;
#pragma unroll
    for (int mt = 0; mt < 2; mt++) {
        const int row = wy * 32 + mt * 16 + g;
#pragma unroll
        for (int nb = 0; nb < 4; nb++)
#pragma unroll
            for (int h = 0; h < 2; h++) {
                const int col = wx * 64 + nb * 16 + h * 8 + 2 * tg2;
                const float b0 = bgate[colBase + col];
                const float b1 = bgate[colBase + col + 1];
                st[row * EPI_PITCH + col]           = acc[mt][nb][h][0] + b0;
                st[row * EPI_PITCH + col + 1]       = acc[mt][nb][h][1] + b1;
                st[(row + 8) * EPI_PITCH + col]     = acc[mt][nb][h][2] + b0;
                st[(row + 8) * EPI_PITCH + col + 1] = acc[mt][nb][h][3] + b1;
            }
    }
    __syncthreads();

    const int uBase = colBase >> 2;
#pragma unroll
    for (int i = 0; i < 16; i++) {
        const int idx = tid + 256 * i;
        const int r = idx >> 5, u = idx & 31;
        const float* gp = st + r * EPI_PITCH + u * 4;
        const float ig = sigm(gp[0]);
        const float fg = sigm(gp[1]);
        const float gg = ftanh(gp[2]);
        const float og = sigm(gp[3]);
        const size_t o = (size_t)(rowBase + r) * 256 + uBase + u;
        const float cv = fg * c0[o] + ig * gg;
        const float hv = og * ftanh(cv);
        c1[o] = cv;
        h1[o] = hv;
        const float rv = fmaxf(hv, 0.f);
        const bf16 hb = __float2bfloat16_rn(rv);
        rhh[o] = hb;
        rhl[o] = __float2bfloat16_rn(rv - __bfloat162float(hb));
    }
}

// =============================================================================
// megasplit: one kernel for all plane splits / permutes / zeroing / biases.
// modes: 0 plain split, 1 gate-perm (1024x256), 2 we->[weL;weR], 3 zero uint2,
//        4 gate bias (bg), 5 uv bias ([be|0])
// =============================================================================
struct Seg { const void* in; void* hi; void* lo; int n; int mode; };
struct SegT { Seg s[15]; int nseg; int total; };

__global__ __launch_bounds__(256) void megasplit(SegT T)
{
    for (int idx = blockIdx.x * 256 + threadIdx.x; idx < T.total;
         idx += gridDim.x * 256) {
        int i = idx, k = 0;
        while (i >= T.s[k].n) { i -= T.s[k].n; k++; }
        const Seg sg = T.s[k];
        if (sg.mode == 0) {
            const float4 v = ((const float4*)sg.in)[i];
            uint32_t h0, l0, h1, l1;
            split2(v.x, v.y, h0, l0);
            split2(v.z, v.w, h1, l1);
            ((uint2*)sg.hi)[i] = make_uint2(h0, h1);
            ((uint2*)sg.lo)[i] = make_uint2(l0, l1);
        } else if (sg.mode == 1) {
            const int r = i >> 6, c = i & 63;
            const int rp = (r & 255) * 4 + (r >> 8);
            const float4 v = ((const float4*)sg.in)[i];
            uint32_t h0, l0, h1, l1;
            split2(v.x, v.y, h0, l0);
            split2(v.z, v.w, h1, l1);
            ((uint2*)sg.hi)[rp * 64 + c] = make_uint2(h0, h1);
            ((uint2*)sg.lo)[rp * 64 + c] = make_uint2(l0, l1);
        } else if (sg.mode == 2) {
            const int r = i >> 6, c4 = i & 63;
            const int orow = (c4 < 32) ? r : 256 + r;
            const int oidx = orow * 32 + (c4 & 31);
            const float4 v = ((const float4*)sg.in)[i];
            uint32_t h0, l0, h1, l1;
            split2(v.x, v.y, h0, l0);
            split2(v.z, v.w, h1, l1);
            ((uint2*)sg.hi)[oidx] = make_uint2(h0, h1);
            ((uint2*)sg.lo)[oidx] = make_uint2(l0, l1);
        } else if (sg.mode == 3) {
            ((uint2*)sg.hi)[i] = make_uint2(0u, 0u);
        } else if (sg.mode == 4) {
            const float b = ((const float*)sg.in)[i] + ((const float*)sg.lo)[i];
            ((float*)sg.hi)[(i & 255) * 4 + (i >> 8)] = b;
        } else {
            ((float*)sg.hi)[i] = (i < 256) ? ((const float*)sg.in)[i] : 0.f;
        }
    }
}

// =============================================================================
// CSR build (4 kernels): hist -> scan1 -> scan3 (inlines block-sum scan) -> scatter
// =============================================================================
__global__ __launch_bounds__(256) void hist_kernel(const int* __restrict__ dst,
                                                   int* __restrict__ cnt)
{
    atomicAdd(&cnt[dst[blockIdx.x * 256 + threadIdx.x]], 1);
}
__global__ __launch_bounds__(256) void scan1_kernel(
    const int* __restrict__ cnt, int* __restrict__ csr, int* __restrict__ bsum)
{
    __shared__ int s[256];
    const int t = threadIdx.x, b = blockIdx.x;
    const int v = cnt[b * 256 + t];
    s[t] = v; __syncthreads();
#pragma unroll
    for (int off = 1; off < 256; off <<= 1) {
        int x = (t >= off) ? s[t - off] : 0;
        __syncthreads();
        s[t] += x;
        __syncthreads();
    }
    csr[b * 256 + t] = s[t] - v;
    if (t == 255) bsum[b] = s[255];
}
__global__ __launch_bounds__(256) void scan3_kernel(
    int* __restrict__ csr, const int* __restrict__ bsum, int* __restrict__ cur)
{
    __shared__ int s[256];
    const int t = threadIdx.x, b = blockIdx.x;
    const int v = bsum[t];
    s[t] = v; __syncthreads();
#pragma unroll
    for (int off = 1; off < 256; off <<= 1) {
        int x = (t >= off) ? s[t - off] : 0;
        __syncthreads();
        s[t] += x;
        __syncthreads();
    }
    const int prefix = s[b] - bsum[b];      // exclusive prefix for block b
    const int i = b * 256 + t;
    const int x = csr[i] + prefix;
    csr[i] = x;
    cur[i] = x;
}
__global__ __launch_bounds__(256) void scatter_src_kernel(
    const int* __restrict__ dst, const int* __restrict__ src,
    int* __restrict__ cur, int* __restrict__ srcv)
{
    const int e = blockIdx.x * 256 + threadIdx.x;
    const int p = atomicAdd(&cur[dst[e]], 1);
    srcv[p] = src[e];
}

// =============================================================================
// Edge gather on combined UV buffer: aggH[d] = sum relu(U[s]+V[d]); deg=cnt
// =============================================================================
__device__ __forceinline__ void unpack8(uint4 h, uint4 l, float* o) {
    const __nv_bfloat162* hp = (const __nv_bfloat162*)&h;
    const __nv_bfloat162* lp = (const __nv_bfloat162*)&l;
#pragma unroll
    for (int j = 0; j < 4; j++) {
        const float2 fh = __bfloat1622float2(hp[j]);
        const float2 fl = __bfloat1622float2(lp[j]);
        o[2 * j] = fh.x + fl.x;
        o[2 * j + 1] = fh.y + fl.y;
    }
}

__global__ __launch_bounds__(256) void gather_kernel(
    const bf16* __restrict__ UVh, const bf16* __restrict__ UVl,
    const int* __restrict__ srcv,
    const int* __restrict__ csr, const int* __restrict__ cnt,
    bf16* __restrict__ aggHh, bf16* __restrict__ aggHl, float* __restrict__ deg)
{
    const int d = blockIdx.x * 8 + (threadIdx.x >> 5);
    const int l = threadIdx.x & 31;
    const int start = csr[d];
    const int n = cnt[d];

    float v[8];
    unpack8(((const uint4*)(UVh + (size_t)d * 512 + 256))[l],
            ((const uint4*)(UVl + (size_t)d * 512 + 256))[l], v);
    float a[8];
#pragma unroll
    for (int j = 0; j < 8; j++) a[j] = 0.f;

    const int nw = n < 32 ? n : 32;
    int myS = 0;
    if (l < nw) myS = srcv[start + l];
    for (int i = 0; i < nw; i++) {
        const int s = __shfl_sync(0xffffffffu, myS, i);
        float u[8];
        unpack8(((const uint4*)(UVh + (size_t)s * 512))[l],
                ((const uint4*)(UVl + (size_t)s * 512))[l], u);
#pragma unroll
        for (int j = 0; j < 8; j++) a[j] += fmaxf(u[j] + v[j], 0.f);
    }
    for (int i = 32; i < n; i++) {
        const int s = srcv[start + i];
        float u[8];
        unpack8(((const uint4*)(UVh + (size_t)s * 512))[l],
                ((const uint4*)(UVl + (size_t)s * 512))[l], u);
#pragma unroll
        for (int j = 0; j < 8; j++) a[j] += fmaxf(u[j] + v[j], 0.f);
    }

    uint4 oh, ol;
    split2(a[0], a[1], oh.x, ol.x);
    split2(a[2], a[3], oh.y, ol.y);
    split2(a[4], a[5], oh.z, ol.z);
    split2(a[6], a[7], oh.w, ol.w);
    ((uint4*)(aggHh + (size_t)d * 256))[l] = oh;
    ((uint4*)(aggHl + (size_t)d * 256))[l] = ol;
    if (l == 0) deg[d] = (float)n;
}

// =============================================================================
// Readout second layer
// =============================================================================
__global__ __launch_bounds__(256) void logits_kernel(
    const bf16* __restrict__ r1h, const bf16* __restrict__ r1l,
    const float* __restrict__ wr2, const float* __restrict__ br2,
    float* __restrict__ out)
{
    __shared__ float sw[8 * 257];
    const int tid = threadIdx.x;
    for (int i = tid; i < 2048; i += 256)
        sw[(i >> 8) * 257 + (i & 255)] = wr2[i];
    __syncthreads();

    const int row = blockIdx.x * 32 + (tid >> 3);
    const int o = tid & 7;
    const __nv_bfloat162* ah = (const __nv_bfloat162*)(r1h + (size_t)row * 256);
    const __nv_bfloat162* al = (const __nv_bfloat162*)(r1l + (size_t)row * 256);
    const float* w = sw + o * 257;
    float acc = 0.f;
#pragma unroll 8
    for (int k = 0; k < 128; k++) {
        const float2 h = __bfloat1622float2(ah[k]);
        const float2 l = __bfloat1622float2(al[k]);
        acc = fmaf(h.x + l.x, w[2 * k], acc);
        acc = fmaf(h.y + l.y, w[2 * k + 1], acc);
    }
    out[(size_t)row * 8 + o] = acc + br2[o];
}

// =============================================================================
// Launcher
// =============================================================================
#define GSYM(var, sym) cudaGetSymbolAddress((void**)&var, sym)

extern "C" void kernel_launch(void* const* d_in, const int* in_sizes, int n_in,
                              void* d_out, int out_size)
{
    const float* obs  = (const float*)d_in[0];
    const float* h0   = (const float*)d_in[1];
    const float* c0   = (const float*)d_in[2];
    const int*   src  = (const int*)d_in[3];
    const int*   dst  = (const int*)d_in[4];
    const float* w1a  = (const float*)d_in[5];
    const float* b1a  = (const float*)d_in[6];
    const float* w1b  = (const float*)d_in[7];
    const float* b1b  = (const float*)d_in[8];
    const float* w_ih = (const float*)d_in[9];
    const float* b_ih = (const float*)d_in[10];
    const float* w_hh = (const float*)d_in[11];
    const float* b_hh = (const float*)d_in[12];
    const float* w1   = (const float*)d_in[13];
    const float* b1   = (const float*)d_in[14];
    const float* we   = (const float*)d_in[15];
    const float* be   = (const float*)d_in[16];
    const float* we2  = (const float*)d_in[17];
    const float* be2  = (const float*)d_in[18];
    const float* wn   = (const float*)d_in[19];
    const float* bn   = (const float*)d_in[20];
    const float* wn2  = (const float*)d_in[21];
    const float* bn2  = (const float*)d_in[22];
    const float* wr   = (const float*)d_in[23];
    const float* br   = (const float*)d_in[24];
    const float* wr2  = (const float*)d_in[25];
    const float* br2  = (const float*)d_in[26];

    float* out    = (float*)d_out;
    float* logits = out;                       // [N, 8]
    float* h1     = out + (size_t)NN * 8;      // [N, 256]
    float* c1     = h1 + (size_t)NN * 256;     // [N, 256]

    bf16 *obsH, *obsL, *h0H, *h0L, *t1H, *t1L, *xH, *xL, *rhH, *rhL,
         *nfH, *nfL, *UVH, *UVL, *aHH, *aHL, *aEH, *aEL, *nhH, *nhL,
         *n2H, *n2L, *r1H, *r1L;
    bf16 *w1aH, *w1aL, *w1bH, *w1bL, *wihH, *wihL, *whhH, *whhL, *w1H, *w1L,
         *wuvH, *wuvL, *we2H, *we2L, *wnH, *wnL, *wn2H, *wn2L, *wrH, *wrL;
    float *p_deg, *p_bg, *p_buv;
    int *p_cnt, *p_csr, *p_cur, *p_srcv, *p_bsum;

    GSYM(obsH, g_obsH); GSYM(obsL, g_obsL); GSYM(h0H, g_h0H); GSYM(h0L, g_h0L);
    GSYM(t1H, g_t1H);   GSYM(t1L, g_t1L);   GSYM(xH, g_xH);   GSYM(xL, g_xL);
    GSYM(rhH, g_rhH);   GSYM(rhL, g_rhL);
    GSYM(nfH, g_nfH);   GSYM(nfL, g_nfL);   GSYM(UVH, g_UVH); GSYM(UVL, g_UVL);
    GSYM(aHH, g_aHH);   GSYM(aHL, g_aHL);
    GSYM(aEH, g_aEH);   GSYM(aEL, g_aEL);   GSYM(nhH, g_nhH); GSYM(nhL, g_nhL);
    GSYM(n2H, g_n2H);   GSYM(n2L, g_n2L);   GSYM(r1H, g_r1H); GSYM(r1L, g_r1L);
    GSYM(w1aH, g_w1aH); GSYM(w1aL, g_w1aL); GSYM(w1bH, g_w1bH); GSYM(w1bL, g_w1bL);
    GSYM(wihH, g_wihH); GSYM(wihL, g_wihL); GSYM(whhH, g_whhH); GSYM(whhL, g_whhL);
    GSYM(w1H, g_w1H);   GSYM(w1L, g_w1L);   GSYM(wuvH, g_wuvH); GSYM(wuvL, g_wuvL);
    GSYM(we2H, g_we2H); GSYM(we2L, g_we2L); GSYM(wnH, g_wnH);   GSYM(wnL, g_wnL);
    GSYM(wn2H, g_wn2H); GSYM(wn2L, g_wn2L); GSYM(wrH, g_wrH);   GSYM(wrL, g_wrL);
    GSYM(p_bg, g_bg);   GSYM(p_buv, g_buv); GSYM(p_deg, g_deg);
    GSYM(p_cnt, g_cnt); GSYM(p_csr, g_csr); GSYM(p_cur, g_cur);
    GSYM(p_srcv, g_srcv); GSYM(p_bsum, g_bsum);

    cudaFuncSetAttribute(tg<1,0,0>, cudaFuncAttributeMaxDynamicSharedMemorySize, TG_SMEM);
    cudaFuncSetAttribute(tg<0,0,0>, cudaFuncAttributeMaxDynamicSharedMemorySize, TG_SMEM);
    cudaFuncSetAttribute(tg<0,1,0>, cudaFuncAttributeMaxDynamicSharedMemorySize, TG_SMEM);
    cudaFuncSetAttribute(tg<1,0,1>, cudaFuncAttributeMaxDynamicSharedMemorySize, TG_SMEM);
    cudaFuncSetAttribute(tglstm, cudaFuncAttributeMaxDynamicSharedMemorySize, TG_SMEM);

    const dim3 blk(256);
    const int MT = NN / 128;   // 512 row tiles

    // ---- one megasplit kernel: all splits/permutes/bias/zero ----
    SegT T;
    int seg = 0, tot = 0;
    auto addseg = [&](const void* in, void* hi, void* lo, int n, int mode) {
        T.s[seg].in = in; T.s[seg].hi = hi; T.s[seg].lo = lo;
        T.s[seg].n = n; T.s[seg].mode = mode;
        seg++; tot += n;
    };
    addseg(obs, obsH, obsL, NN * 256 / 4, 0);
    addseg(h0, h0H, h0L, NN * 256 / 4, 0);
    addseg(w_ih, wihH, wihL, 1024 * 256 / 4, 1);
    addseg(w_hh, whhH, whhL, 1024 * 256 / 4, 1);
    addseg(w1a, w1aH, w1aL, 512 * 256 / 4, 0);
    addseg(w1b, w1bH, w1bL, 256 * 512 / 4, 0);
    addseg(we, wuvH, wuvL, 256 * 256 / 4, 2);
    addseg(wn, wnH, wnL, 256 * 256 / 4, 0);
    addseg(w1, w1H, w1L, 128 * 256 / 4, 0);
    addseg(we2, we2H, we2L, 128 * 256 / 4, 0);
    addseg(wn2, wn2H, wn2L, 128 * 256 / 4, 0);
    addseg(wr, wrH, wrL, 256 * 128 / 4, 0);
    addseg(nullptr, p_cnt, nullptr, NN / 2, 3);
    addseg(b_ih, p_bg, (void*)b_hh, 1024, 4);
    addseg(be, p_buv, nullptr, 512, 5);
    T.nseg = seg; T.total = tot;
    megasplit<<<2048, blk>>>(T);

    // ---- CSR build (4 kernels) ----
    hist_kernel<<<EE / 256, blk>>>(dst, p_cnt);
    scan1_kernel<<<256, blk>>>(p_cnt, p_csr, p_bsum);
    scan3_kernel<<<256, blk>>>(p_csr, p_bsum, p_cur);
    scatter_src_kernel<<<EE / 256, blk>>>(dst, src, p_cur, p_srcv);

    // 1. t1 = relu(obs @ w1a^T + b1a)                        [N,512] K=256
    tg<1,0,0><<<dim3(4, MT), blk, TG_SMEM>>>(obsH, obsL, nullptr, nullptr, 256,
                                             w1aH, w1aL, nullptr, nullptr, 256, 256,
                                             b1a, nullptr, nullptr, t1H, t1L, 512);
    // 2. x = t1 @ w1b^T + b1b                                [N,256] K=512
    tg<0,0,0><<<dim3(2, MT), blk, TG_SMEM>>>(t1H, t1L, nullptr, nullptr, 512,
                                             w1bH, w1bL, nullptr, nullptr, 512, 512,
                                             b1b, nullptr, nullptr, xH, xL, 256);
    // 3+4. fused gates GEMM + LSTM -> h1, c1, relu(h1) planes
    tglstm<<<dim3(8, MT), blk, TG_SMEM>>>(xH, xL, h0H, h0L, 256,
                                          wihH, wihL, whhH, whhL, 256, 256,
                                          p_bg, c0, h1, c1, rhH, rhL);
    // 5. nf = relu(h1) @ w1^T + b1                           [N,128] K=256
    tg<0,0,0><<<dim3(1, MT), blk, TG_SMEM>>>(rhH, rhL, nullptr, nullptr, 256,
                                             w1H, w1L, nullptr, nullptr, 256, 256,
                                             b1, nullptr, nullptr, nfH, nfL, 128);
    // 6. [U|V] = nf @ wuv^T + [be|0]                         [N,512] K=128
    tg<0,0,0><<<dim3(4, MT), blk, TG_SMEM>>>(nfH, nfL, nullptr, nullptr, 128,
                                             wuvH, wuvL, nullptr, nullptr, 128, 128,
                                             p_buv, nullptr, nullptr, UVH, UVL, 512);
    // 7. gather: aggH[d] = sum relu(U[src]+V[d]); deg[d]=cnt[d]
    gather_kernel<<<NN / 8, blk>>>(UVH, UVL, p_srcv, p_csr, p_cnt,
                                   aHH, aHL, p_deg);
    // 8. aggE = aggH @ we2^T + deg*be2                       [N,128] K=256
    tg<0,1,0><<<dim3(1, MT), blk, TG_SMEM>>>(aHH, aHL, nullptr, nullptr, 256,
                                             we2H, we2L, nullptr, nullptr, 256, 256,
                                             be2, nullptr, p_deg, aEH, aEL, 128);
    // 9. nh = relu(nf@wnL^T + aggE@wnR^T + bn)               [N,256]
    tg<1,0,1><<<dim3(2, MT), blk, TG_SMEM>>>(nfH, nfL, aEH, aEL, 128,
                                             wnH, wnL, wnH + 128, wnL + 128, 256, 128,
                                             bn, nullptr, nullptr, nhH, nhL, 256);
    // 10. nf2 = nh @ wn2^T + bn2                             [N,128] K=256
    tg<0,0,0><<<dim3(1, MT), blk, TG_SMEM>>>(nhH, nhL, nullptr, nullptr, 256,
                                             wn2H, wn2L, nullptr, nullptr, 256, 256,
                                             bn2, nullptr, nullptr, n2H, n2L, 128);
    // 11. r1 = relu(nf2 @ wr^T + br)                         [N,256] K=128
    tg<1,0,0><<<dim3(2, MT), blk, TG_SMEM>>>(n2H, n2L, nullptr, nullptr, 128,
                                             wrH, wrL, nullptr, nullptr, 128, 128,
                                             br, nullptr, nullptr, r1H, r1L, 256);
    // 12. logits = r1 @ wr2^T + br2                          [N,8]
    logits_kernel<<<NN / 32, blk>>>(r1H, r1L, wr2, br2, logits);
}